// round 6
// baseline (speedup 1.0000x reference)
#include <cuda_runtime.h>
#include <cuda_bf16.h>
#include <math.h>

// Problem constants
#define B 2
#define S 2048
#define EMB 2048
#define NH 32
#define NKV 8
#define HD 64
#define KV_DIM (NKV * HD)   // 512
#define M_ROWS (B * S)      // 4096

// Scratch (device globals; no allocation allowed)
__device__ float g_Q[M_ROWS * EMB];      // 32 MB
__device__ float g_K[M_ROWS * KV_DIM];   //  8 MB
__device__ float g_V[M_ROWS * KV_DIM];   //  8 MB
__device__ float g_C[M_ROWS * EMB];      // 32 MB

// ---------------------------------------------------------------------------
// Helpers
// ---------------------------------------------------------------------------
__device__ __forceinline__ unsigned f2tf32(float x) {
    unsigned r; asm("cvt.rna.tf32.f32 %0, %1;" : "=r"(r) : "f"(x)); return r;
}
__device__ __forceinline__ float ex2f_fast(float x) {
    float r; asm("ex2.approx.f32 %0, %1;" : "=f"(r) : "f"(x)); return r;
}
// D += A(16x8,row) * B(8x8,col), tf32 inputs, f32 accum
__device__ __forceinline__ void mma8(float* c, unsigned a0, unsigned a1,
                                     unsigned a2, unsigned a3,
                                     unsigned b0, unsigned b1) {
    asm volatile(
        "mma.sync.aligned.m16n8k8.row.col.f32.tf32.tf32.f32 "
        "{%0,%1,%2,%3}, {%4,%5,%6,%7}, {%8,%9}, {%0,%1,%2,%3};"
        : "+f"(c[0]), "+f"(c[1]), "+f"(c[2]), "+f"(c[3])
        : "r"(a0), "r"(a1), "r"(a2), "r"(a3), "r"(b0), "r"(b1));
}

// ---------------------------------------------------------------------------
// tf32 tensor-core GEMM: C[M,N] = A[M,K] * Bm[K,N], row-major fp32.
// 128x128 block tile, BK=16, 256 threads (8 warps, 4x2 warp grid, 32x64/warp).
// Both A and B^T stored k-permuted (k' = (k%4)*4 + k/4) so every fragment
// load is one conflict-free LDS.128 covering both k-steps of the chunk.
// ---------------------------------------------------------------------------
__global__ void __launch_bounds__(256)
gemm_tf32(const float* __restrict__ A, const float* __restrict__ Bm,
          float* __restrict__ C, int M, int N, int K)
{
    __shared__ __align__(16) unsigned As[2][128][16];
    __shared__ __align__(16) unsigned Bs[2][128][16];   // B transposed [n][k']

    const int tid  = threadIdx.x;
    const int lane = tid & 31;
    const int warp = tid >> 5;
    const int wm = warp >> 1, wn = warp & 1;
    const int g = lane >> 2, j = lane & 3;
    const int bm = blockIdx.y * 128, bn = blockIdx.x * 128;

    // loader mapping
    const int arow = tid >> 2;            // 0..63 (and +64)
    const int aq   = tid & 3;             // k-group of 4
    const int brow = tid & 15;            // k 0..15
    const int bcol = (tid >> 4) * 8;      // n base 0..120
    const int bkp  = (brow & 3) * 4 + (brow >> 2);   // permuted k slot

    const float* Ap = A  + (size_t)(bm + arow) * K + aq * 4;
    const float* Bp = Bm + (size_t)brow * N + bn + bcol;

    float4 aR0 = *(const float4*)Ap;
    float4 aR1 = *(const float4*)(Ap + (size_t)64 * K);
    float4 bR0 = *(const float4*)Bp;
    float4 bR1 = *(const float4*)(Bp + 4);

    float c[2][8][4];
    #pragma unroll
    for (int mt = 0; mt < 2; mt++)
        #pragma unroll
        for (int nt = 0; nt < 8; nt++)
            #pragma unroll
            for (int e = 0; e < 4; e++) c[mt][nt][e] = 0.f;

    const int nc = K / 16;
    for (int ci = 0; ci < nc; ci++) {
        const int buf = ci & 1;
        // stage regs -> smem (A permuted scatter; B transposed permuted scatter)
        {
            unsigned* ad = &As[buf][arow][aq];
            ad[0]  = f2tf32(aR0.x); ad[4]  = f2tf32(aR0.y);
            ad[8]  = f2tf32(aR0.z); ad[12] = f2tf32(aR0.w);
            unsigned* ad2 = &As[buf][arow + 64][aq];
            ad2[0]  = f2tf32(aR1.x); ad2[4]  = f2tf32(aR1.y);
            ad2[8]  = f2tf32(aR1.z); ad2[12] = f2tf32(aR1.w);
            Bs[buf][bcol + 0][bkp] = f2tf32(bR0.x);
            Bs[buf][bcol + 1][bkp] = f2tf32(bR0.y);
            Bs[buf][bcol + 2][bkp] = f2tf32(bR0.z);
            Bs[buf][bcol + 3][bkp] = f2tf32(bR0.w);
            Bs[buf][bcol + 4][bkp] = f2tf32(bR1.x);
            Bs[buf][bcol + 5][bkp] = f2tf32(bR1.y);
            Bs[buf][bcol + 6][bkp] = f2tf32(bR1.z);
            Bs[buf][bcol + 7][bkp] = f2tf32(bR1.w);
        }
        __syncthreads();

        // prefetch next chunk into regs (overlaps with MMA below)
        if (ci + 1 < nc) {
            Ap += 16; Bp += (size_t)16 * N;
            aR0 = *(const float4*)Ap;
            aR1 = *(const float4*)(Ap + (size_t)64 * K);
            bR0 = *(const float4*)Bp;
            bR1 = *(const float4*)(Bp + 4);
        }

        // fragments: one LDS.128 each, covering both k-steps
        uint4 av[2][2];
        #pragma unroll
        for (int mt = 0; mt < 2; mt++) {
            av[mt][0] = *(const uint4*)&As[buf][wm * 32 + mt * 16 + g][j * 4];
            av[mt][1] = *(const uint4*)&As[buf][wm * 32 + mt * 16 + g + 8][j * 4];
        }
        uint4 bv[8];
        #pragma unroll
        for (int nt = 0; nt < 8; nt++)
            bv[nt] = *(const uint4*)&Bs[buf][wn * 64 + nt * 8 + g][j * 4];

        #pragma unroll
        for (int ks = 0; ks < 2; ks++) {
            #pragma unroll
            for (int mt = 0; mt < 2; mt++) {
                unsigned a0, a1, a2, a3;
                if (ks == 0) { a0 = av[mt][0].x; a1 = av[mt][1].x; a2 = av[mt][0].y; a3 = av[mt][1].y; }
                else         { a0 = av[mt][0].z; a1 = av[mt][1].z; a2 = av[mt][0].w; a3 = av[mt][1].w; }
                #pragma unroll
                for (int nt = 0; nt < 8; nt++) {
                    unsigned b0 = (ks == 0) ? bv[nt].x : bv[nt].z;
                    unsigned b1 = (ks == 0) ? bv[nt].y : bv[nt].w;
                    mma8(c[mt][nt], a0, a1, a2, a3, b0, b1);
                }
            }
        }
        // single sync per iter: double-buffered smem, matched barrier.
    }

    #pragma unroll
    for (int mt = 0; mt < 2; mt++) {
        int r0 = bm + wm * 32 + mt * 16 + g;
        #pragma unroll
        for (int nt = 0; nt < 8; nt++) {
            int col = bn + wn * 64 + nt * 8 + 2 * j;
            *(float2*)&C[(size_t)r0 * N + col]       = make_float2(c[mt][nt][0], c[mt][nt][1]);
            *(float2*)&C[(size_t)(r0 + 8) * N + col] = make_float2(c[mt][nt][2], c[mt][nt][3]);
        }
    }
}

// ---------------------------------------------------------------------------
// Flash attention with tf32 mma, GQA-shared K/V.
// Block = (32 q-rows x 4 q-heads of one kv head, batch), 256 thr, 8 warps.
// Warp w: q-head kvh*4 + (w>>1), rows q0 + (w&1)*16 .. +16.
// K/V chunks of 64 tokens in smem (transposed + k-permuted + stride-80 pad),
// shared by all 8 warps. Q frags in registers. P via per-warp smem.
// ---------------------------------------------------------------------------
#define ATTN_SMEM (2 * 64 * 80 * 4 + 8 * 16 * 80 * 4)   // 81920 bytes

__global__ void __launch_bounds__(256)
attn_tf32(const float* __restrict__ Q, const float* __restrict__ Kg,
          const float* __restrict__ Vg, float* __restrict__ ctx)
{
    extern __shared__ __align__(16) unsigned smu[];
    unsigned* Ks = smu;                      // [64 tok][80]  (d permuted)
    unsigned* Vs = smu + 64 * 80;            // [64 d][80]    (tok permuted)
    unsigned* Ps = smu + 2 * 64 * 80 + (threadIdx.x >> 5) * 16 * 80;  // per-warp

    const int tid  = threadIdx.x;
    const int lane = tid & 31;
    const int warp = tid >> 5;
    const int g = lane >> 2, j = lane & 3;
    const int kvh = blockIdx.y, b = blockIdx.z;
    const int h = kvh * 4 + (warp >> 1);     // q-head for this warp
    const int q0 = blockIdx.x * 32 + (warp & 1) * 16;   // warp's 16 q-rows

    // Preload Q fragments (pre-scaled by 1/sqrt(D) * log2(e) for ex2 softmax)
    unsigned qa[8][4];
    {
        const float* qp = Q + ((size_t)(b * S + q0 + g)) * EMB + h * HD;
        const float qs = 0.125f * 1.4426950408889634f;
        #pragma unroll
        for (int ks = 0; ks < 8; ks++) {
            qa[ks][0] = f2tf32(qp[ks * 8 + j] * qs);
            qa[ks][1] = f2tf32(qp[(size_t)8 * EMB + ks * 8 + j] * qs);
            qa[ks][2] = f2tf32(qp[ks * 8 + j + 4] * qs);
            qa[ks][3] = f2tf32(qp[(size_t)8 * EMB + ks * 8 + j + 4] * qs);
        }
    }

    float m0 = -1e30f, m1 = -1e30f, l0 = 0.f, l1 = 0.f;
    float o[8][4];
    #pragma unroll
    for (int nt = 0; nt < 8; nt++)
        #pragma unroll
        for (int e = 0; e < 4; e++) o[nt][e] = 0.f;

    for (int k0 = 0; k0 < S; k0 += 64) {
        // --- load K/V chunk (transpose + permute + tf32), 256 threads ---
        #pragma unroll
        for (int i = 0; i < 4; i++) {
            int f4  = i * 256 + tid;         // 0..1023 float4 units
            int tok = f4 >> 4;
            int q4  = f4 & 15;
            size_t grow = ((size_t)(b * S + k0 + tok)) * KV_DIM + kvh * HD + q4 * 4;
            float4 kv = *(const float4*)&Kg[grow];
            unsigned* kd = Ks + tok * 80 + (q4 >> 2) * 16 + (q4 & 3);
            kd[0]  = f2tf32(kv.x); kd[4]  = f2tf32(kv.y);
            kd[8]  = f2tf32(kv.z); kd[12] = f2tf32(kv.w);
            float4 vv = *(const float4*)&Vg[grow];
            int tkl  = tok & 15;
            int tokp = (tok & 48) + (tkl & 3) * 4 + (tkl >> 2);
            unsigned* vd = Vs + (q4 * 4) * 80 + tokp;
            vd[0]   = f2tf32(vv.x); vd[80]  = f2tf32(vv.y);
            vd[160] = f2tf32(vv.z); vd[240] = f2tf32(vv.w);
        }
        __syncthreads();

        // --- scores: S = Q * K^T (16 x 64 per warp) ---
        float s[8][4];
        #pragma unroll
        for (int nt = 0; nt < 8; nt++)
            #pragma unroll
            for (int e = 0; e < 4; e++) s[nt][e] = 0.f;

        #pragma unroll
        for (int k2 = 0; k2 < 4; k2++) {
            uint4 kb[8];
            #pragma unroll
            for (int nt = 0; nt < 8; nt++)
                kb[nt] = *(const uint4*)&Ks[(nt * 8 + g) * 80 + k2 * 16 + j * 4];
            #pragma unroll
            for (int nt = 0; nt < 8; nt++) {
                mma8(s[nt], qa[2*k2][0], qa[2*k2][1], qa[2*k2][2], qa[2*k2][3],
                     kb[nt].x, kb[nt].y);
                mma8(s[nt], qa[2*k2+1][0], qa[2*k2+1][1], qa[2*k2+1][2], qa[2*k2+1][3],
                     kb[nt].z, kb[nt].w);
            }
        }

        // --- online softmax (log2 domain) ---
        float r0 = -1e30f, r1 = -1e30f;
        #pragma unroll
        for (int nt = 0; nt < 8; nt++) {
            r0 = fmaxf(r0, fmaxf(s[nt][0], s[nt][1]));
            r1 = fmaxf(r1, fmaxf(s[nt][2], s[nt][3]));
        }
        r0 = fmaxf(r0, __shfl_xor_sync(0xffffffffu, r0, 1));
        r0 = fmaxf(r0, __shfl_xor_sync(0xffffffffu, r0, 2));
        r1 = fmaxf(r1, __shfl_xor_sync(0xffffffffu, r1, 1));
        r1 = fmaxf(r1, __shfl_xor_sync(0xffffffffu, r1, 2));
        float mn0 = fmaxf(m0, r0), mn1 = fmaxf(m1, r1);
        float sc0 = ex2f_fast(m0 - mn0), sc1 = ex2f_fast(m1 - mn1);
        float rs0 = 0.f, rs1 = 0.f;
        #pragma unroll
        for (int nt = 0; nt < 8; nt++) {
            int t0 = nt * 8 + 2 * j, t1 = t0 + 1;
            int t0p = (t0 & 48) + ((t0 & 15) & 3) * 4 + ((t0 & 15) >> 2);
            int t1p = (t1 & 48) + ((t1 & 15) & 3) * 4 + ((t1 & 15) >> 2);
            float p0 = ex2f_fast(s[nt][0] - mn0);
            float p1 = ex2f_fast(s[nt][1] - mn0);
            float p2 = ex2f_fast(s[nt][2] - mn1);
            float p3 = ex2f_fast(s[nt][3] - mn1);
            rs0 += p0 + p1; rs1 += p2 + p3;
            Ps[g * 80 + t0p]       = f2tf32(p0);
            Ps[g * 80 + t1p]       = f2tf32(p1);
            Ps[(g + 8) * 80 + t0p] = f2tf32(p2);
            Ps[(g + 8) * 80 + t1p] = f2tf32(p3);
            o[nt][0] *= sc0; o[nt][1] *= sc0;
            o[nt][2] *= sc1; o[nt][3] *= sc1;
        }
        rs0 += __shfl_xor_sync(0xffffffffu, rs0, 1);
        rs0 += __shfl_xor_sync(0xffffffffu, rs0, 2);
        rs1 += __shfl_xor_sync(0xffffffffu, rs1, 1);
        rs1 += __shfl_xor_sync(0xffffffffu, rs1, 2);
        l0 = l0 * sc0 + rs0; m0 = mn0;
        l1 = l1 * sc1 + rs1; m1 = mn1;
        __syncwarp();   // Ps is per-warp private; order STS before LDS

        // --- O += P * V ---
        #pragma unroll
        for (int k2 = 0; k2 < 4; k2++) {
            uint4 pa0 = *(const uint4*)&Ps[g * 80 + k2 * 16 + j * 4];
            uint4 pa1 = *(const uint4*)&Ps[(g + 8) * 80 + k2 * 16 + j * 4];
            #pragma unroll
            for (int nt = 0; nt < 8; nt++) {
                uint4 vb = *(const uint4*)&Vs[(nt * 8 + g) * 80 + k2 * 16 + j * 4];
                mma8(o[nt], pa0.x, pa1.x, pa0.y, pa1.y, vb.x, vb.y);
                mma8(o[nt], pa0.z, pa1.z, pa0.w, pa1.w, vb.z, vb.w);
            }
        }
        __syncthreads();   // protect K/V smem before next chunk overwrites
    }

    // --- normalize + store ---
    float inv0 = 1.f / l0, inv1 = 1.f / l1;
    size_t row = (size_t)(b * S + q0 + g);
    #pragma unroll
    for (int nt = 0; nt < 8; nt++) {
        int col = h * HD + nt * 8 + 2 * j;
        *(float2*)&ctx[row * EMB + col]       = make_float2(o[nt][0] * inv0, o[nt][1] * inv0);
        *(float2*)&ctx[(row + 8) * EMB + col] = make_float2(o[nt][2] * inv1, o[nt][3] * inv1);
    }
}

// ---------------------------------------------------------------------------
extern "C" void kernel_launch(void* const* d_in, const int* in_sizes, int n_in,
                              void* d_out, int out_size)
{
    const float* query = (const float*)d_in[0];
    const float* key   = (const float*)d_in[1];
    const float* value = (const float*)d_in[2];
    const float* Wq    = (const float*)d_in[3];
    const float* Wk    = (const float*)d_in[4];
    const float* Wv    = (const float*)d_in[5];
    const float* Wo    = (const float*)d_in[6];
    float* out = (float*)d_out;

    float *gQ, *gK, *gV, *gC;
    cudaGetSymbolAddress((void**)&gQ, g_Q);
    cudaGetSymbolAddress((void**)&gK, g_K);
    cudaGetSymbolAddress((void**)&gV, g_V);
    cudaGetSymbolAddress((void**)&gC, g_C);

    cudaFuncSetAttribute(attn_tf32, cudaFuncAttributeMaxDynamicSharedMemorySize, ATTN_SMEM);

    // Projections (tensor cores, tf32)
    gemm_tf32<<<dim3(EMB / 128,    M_ROWS / 128), 256>>>(query, Wq, gQ, M_ROWS, EMB,    EMB);
    gemm_tf32<<<dim3(KV_DIM / 128, M_ROWS / 128), 256>>>(key,   Wk, gK, M_ROWS, KV_DIM, EMB);
    gemm_tf32<<<dim3(KV_DIM / 128, M_ROWS / 128), 256>>>(value, Wv, gV, M_ROWS, KV_DIM, EMB);

    // Attention (tensor cores, tf32, flash, GQA-shared K/V)
    attn_tf32<<<dim3(S / 32, NKV, B), 256, ATTN_SMEM>>>(gQ, gK, gV, gC);

    // Output projection
    gemm_tf32<<<dim3(EMB / 128, M_ROWS / 128), 256>>>(gC, Wo, out, M_ROWS, EMB, EMB);
}

// round 8
// speedup vs baseline: 1.7381x; 1.7381x over previous
#include <cuda_runtime.h>
#include <cuda_fp16.h>
#include <math.h>

// Problem constants
#define B 2
#define S 2048
#define EMB 2048
#define NH 32
#define NKV 8
#define HD 64
#define KV_DIM (NKV * HD)   // 512
#define M_ROWS (B * S)      // 4096

// Scratch (device globals; no allocation allowed)
__device__ float g_Q[M_ROWS * EMB];      // 32 MB
__device__ float g_K[M_ROWS * KV_DIM];   //  8 MB
__device__ float g_V[M_ROWS * KV_DIM];   //  8 MB
__device__ float g_C[M_ROWS * EMB];      // 32 MB

// ---------------------------------------------------------------------------
// Helpers
// ---------------------------------------------------------------------------
__device__ __forceinline__ unsigned packh2(float a, float b) {
    __half2 h = __floats2half2_rn(a, b);      // .x = a (lo), .y = b (hi)
    return *reinterpret_cast<unsigned*>(&h);
}
__device__ __forceinline__ float ex2f_fast(float x) {
    float r; asm("ex2.approx.f32 %0, %1;" : "=f"(r) : "f"(x)); return r;
}
// D += A(16x16,row) * B(16x8,col), fp16 inputs, f32 accum
__device__ __forceinline__ void mma16(float* c, unsigned a0, unsigned a1,
                                      unsigned a2, unsigned a3,
                                      unsigned b0, unsigned b1) {
    asm volatile(
        "mma.sync.aligned.m16n8k16.row.col.f32.f16.f16.f32 "
        "{%0,%1,%2,%3}, {%4,%5,%6,%7}, {%8,%9}, {%0,%1,%2,%3};"
        : "+f"(c[0]), "+f"(c[1]), "+f"(c[2]), "+f"(c[3])
        : "r"(a0), "r"(a1), "r"(a2), "r"(a3), "r"(b0), "r"(b1));
}

// ---------------------------------------------------------------------------
// fp16 tensor-core GEMM: C[M,N] = A[M,K] * Bm[K,N], fp32 in/out.
// 128x128 tile, BK=32, 256 threads (8 warps, 4x2, 32x64 per warp).
// Smem = half2 words. A slot-permuted (word k2 -> slot 4*(k2&3)+(k2>>2)):
// one uint4 A-frag read covers both k16-steps. B rows k2 x 128 words,
// padded to 136 (scalar frag reads hit banks 8j+g: conflict-free).
// blockIdx.z selects (A0,B0,C0) or (A1,B1,C1) so K+V projections fuse.
// ---------------------------------------------------------------------------
__global__ void __launch_bounds__(256, 2)
gemm_f16(const float* __restrict__ A0, const float* __restrict__ A1,
         const float* __restrict__ B0, const float* __restrict__ B1,
         float* __restrict__ C0, float* __restrict__ C1,
         int M, int N, int K)
{
    __shared__ __align__(16) unsigned As[2][128][16];
    __shared__ __align__(16) unsigned Bs[2][16][136];

    const float* A  = (blockIdx.z == 0) ? A0 : A1;
    const float* Bm = (blockIdx.z == 0) ? B0 : B1;
    float*       C  = (blockIdx.z == 0) ? C0 : C1;

    const int tid  = threadIdx.x;
    const int lane = tid & 31;
    const int warp = tid >> 5;
    const int wm = warp >> 1, wn = warp & 1;
    const int g = lane >> 2, j = lane & 3;
    const int bm = blockIdx.y * 128, bn = blockIdx.x * 128;

    // loader mapping
    const int arow = tid >> 2;          // 0..63 (and +64)
    const int aq   = tid & 3;           // k-group: k = aq*8 .. aq*8+7
    const int bk2  = tid & 15;          // k2 row (k = 2*bk2, 2*bk2+1)
    const int bnb  = (tid >> 4) * 8;    // n base 0..120

    const float* Ap  = A  + (size_t)(bm + arow) * K + aq * 8;
    const float* Bp0 = Bm + (size_t)(2 * bk2) * N + bn + bnb;

    float4 a00 = *(const float4*)Ap;
    float4 a01 = *(const float4*)(Ap + 4);
    float4 a10 = *(const float4*)(Ap + (size_t)64 * K);
    float4 a11 = *(const float4*)(Ap + (size_t)64 * K + 4);
    float4 b00 = *(const float4*)Bp0;
    float4 b01 = *(const float4*)(Bp0 + 4);
    float4 b10 = *(const float4*)(Bp0 + N);
    float4 b11 = *(const float4*)(Bp0 + N + 4);

    float c[2][8][4];
    #pragma unroll
    for (int mt = 0; mt < 2; mt++)
        #pragma unroll
        for (int nt = 0; nt < 8; nt++)
            #pragma unroll
            for (int e = 0; e < 4; e++) c[mt][nt][e] = 0.f;

    const int nc = K / 32;
    for (int ci = 0; ci < nc; ci++) {
        const int buf = ci & 1;
        // stage regs -> smem (A: slot = 4m + aq; B: half2 over k-rows, uint4)
        {
            unsigned* ad = &As[buf][arow][aq];
            ad[0]  = packh2(a00.x, a00.y);
            ad[4]  = packh2(a00.z, a00.w);
            ad[8]  = packh2(a01.x, a01.y);
            ad[12] = packh2(a01.z, a01.w);
            unsigned* ad2 = &As[buf][arow + 64][aq];
            ad2[0]  = packh2(a10.x, a10.y);
            ad2[4]  = packh2(a10.z, a10.w);
            ad2[8]  = packh2(a11.x, a11.y);
            ad2[12] = packh2(a11.z, a11.w);
            uint4 w0 = make_uint4(packh2(b00.x, b10.x), packh2(b00.y, b10.y),
                                  packh2(b00.z, b10.z), packh2(b00.w, b10.w));
            uint4 w1 = make_uint4(packh2(b01.x, b11.x), packh2(b01.y, b11.y),
                                  packh2(b01.z, b11.z), packh2(b01.w, b11.w));
            *(uint4*)&Bs[buf][bk2][bnb]     = w0;
            *(uint4*)&Bs[buf][bk2][bnb + 4] = w1;
        }
        __syncthreads();

        // prefetch next chunk (overlaps MMA)
        if (ci + 1 < nc) {
            Ap += 32; Bp0 += (size_t)32 * N;
            a00 = *(const float4*)Ap;
            a01 = *(const float4*)(Ap + 4);
            a10 = *(const float4*)(Ap + (size_t)64 * K);
            a11 = *(const float4*)(Ap + (size_t)64 * K + 4);
            b00 = *(const float4*)Bp0;
            b01 = *(const float4*)(Bp0 + 4);
            b10 = *(const float4*)(Bp0 + N);
            b11 = *(const float4*)(Bp0 + N + 4);
        }

        // A fragments: one LDS.128 per (mt,row-half) covers both k-steps
        uint4 av[2][2];
        #pragma unroll
        for (int mt = 0; mt < 2; mt++) {
            av[mt][0] = *(const uint4*)&As[buf][wm * 32 + mt * 16 + g][j * 4];
            av[mt][1] = *(const uint4*)&As[buf][wm * 32 + mt * 16 + g + 8][j * 4];
        }
        #pragma unroll
        for (int ks = 0; ks < 2; ks++) {
            unsigned bb[8][2];
            #pragma unroll
            for (int nt = 0; nt < 8; nt++) {
                int col = wn * 64 + nt * 8 + g;
                bb[nt][0] = Bs[buf][ks * 8 + j][col];
                bb[nt][1] = Bs[buf][ks * 8 + j + 4][col];
            }
            #pragma unroll
            for (int mt = 0; mt < 2; mt++) {
                unsigned A0r, A1r, A2r, A3r;
                if (ks == 0) { A0r = av[mt][0].x; A1r = av[mt][1].x; A2r = av[mt][0].y; A3r = av[mt][1].y; }
                else         { A0r = av[mt][0].z; A1r = av[mt][1].z; A2r = av[mt][0].w; A3r = av[mt][1].w; }
                #pragma unroll
                for (int nt = 0; nt < 8; nt++)
                    mma16(c[mt][nt], A0r, A1r, A2r, A3r, bb[nt][0], bb[nt][1]);
            }
        }
    }

    #pragma unroll
    for (int mt = 0; mt < 2; mt++) {
        int r0 = bm + wm * 32 + mt * 16 + g;
        #pragma unroll
        for (int nt = 0; nt < 8; nt++) {
            int col = bn + wn * 64 + nt * 8 + 2 * j;
            *(float2*)&C[(size_t)r0 * N + col]       = make_float2(c[mt][nt][0], c[mt][nt][1]);
            *(float2*)&C[(size_t)(r0 + 8) * N + col] = make_float2(c[mt][nt][2], c[mt][nt][3]);
        }
    }
}

// ---------------------------------------------------------------------------
// Flash attention, fp16 mma, GQA-shared K/V, P in registers.
// Block = (32 q-rows x 4 q-heads of one kv head), 256 thr, 8 warps.
// Ks2[tok][48]: half2 d-pairs slot-permuted; Vs2[d][48]: half2 tok-pairs
// slot-permuted. Stride 48 -> LDS.128 phase quads 4(g&1)+4T+j distinct:
// conflict-free.
// ---------------------------------------------------------------------------
__device__ __forceinline__ int slotp(int w) {   // w in 0..31 (half2 index)
    return ((w >> 4) << 4) + ((w & 3) * 4) + ((w & 15) >> 2);
}

__global__ void __launch_bounds__(256, 2)
attn_f16(const float* __restrict__ Q, const float* __restrict__ Kg,
         const float* __restrict__ Vg, float* __restrict__ ctx)
{
    __shared__ __align__(16) unsigned Ks2[64][48];
    __shared__ __align__(16) unsigned Vs2[64][48];

    const int tid  = threadIdx.x;
    const int lane = tid & 31;
    const int warp = tid >> 5;
    const int g = lane >> 2, j = lane & 3;
    const int kvh = blockIdx.y, b = blockIdx.z;
    const int h  = kvh * 4 + (warp >> 1);
    const int q0 = blockIdx.x * 32 + (warp & 1) * 16;

    // Q fragments, pre-scaled by 1/sqrt(D)*log2(e): qa[step t][a0..a3]
    unsigned qa[4][4];
    {
        const float* qp  = Q + ((size_t)(b * S + q0 + g)) * EMB + h * HD;
        const float* qp8 = qp + (size_t)8 * EMB;
        const float qs = 0.125f * 1.4426950408889634f;
        #pragma unroll
        for (int t = 0; t < 4; t++) {
            int d0 = t * 16 + 2 * j;
            qa[t][0] = packh2(qp[d0] * qs,      qp[d0 + 1] * qs);
            qa[t][1] = packh2(qp8[d0] * qs,     qp8[d0 + 1] * qs);
            qa[t][2] = packh2(qp[d0 + 8] * qs,  qp[d0 + 9] * qs);
            qa[t][3] = packh2(qp8[d0 + 8] * qs, qp8[d0 + 9] * qs);
        }
    }

    float m0 = -1e30f, m1 = -1e30f, l0 = 0.f, l1 = 0.f;
    float o[8][4];
    #pragma unroll
    for (int nt = 0; nt < 8; nt++)
        #pragma unroll
        for (int e = 0; e < 4; e++) o[nt][e] = 0.f;

    for (int k0 = 0; k0 < S; k0 += 64) {
        // --- K loader: 64 tok x 64 d floats; words = half2 over d ---
        #pragma unroll
        for (int i = 0; i < 4; i++) {
            int f4  = i * 256 + tid;
            int tok = f4 >> 4;
            int q4  = f4 & 15;
            float4 kv = *(const float4*)&Kg[((size_t)(b * S + k0 + tok)) * KV_DIM + kvh * HD + q4 * 4];
            Ks2[tok][slotp(2 * q4)]     = packh2(kv.x, kv.y);
            Ks2[tok][slotp(2 * q4 + 1)] = packh2(kv.z, kv.w);
        }
        // --- V loader: words = half2 over token pairs ---
        #pragma unroll
        for (int i = 0; i < 2; i++) {
            int idx = i * 256 + tid;
            int tp  = idx >> 4;          // token pair 0..31
            int d4  = idx & 15;          // d group of 4
            size_t base = ((size_t)(b * S + k0 + 2 * tp)) * KV_DIM + kvh * HD + d4 * 4;
            float4 v0 = *(const float4*)&Vg[base];
            float4 v1 = *(const float4*)&Vg[base + KV_DIM];
            int sl = slotp(tp);
            Vs2[d4 * 4 + 0][sl] = packh2(v0.x, v1.x);
            Vs2[d4 * 4 + 1][sl] = packh2(v0.y, v1.y);
            Vs2[d4 * 4 + 2][sl] = packh2(v0.z, v1.z);
            Vs2[d4 * 4 + 3][sl] = packh2(v0.w, v1.w);
        }
        __syncthreads();

        // --- scores: S = Q * K^T (16 x 64 per warp) ---
        float s[8][4];
        #pragma unroll
        for (int nt = 0; nt < 8; nt++)
            #pragma unroll
            for (int e = 0; e < 4; e++) s[nt][e] = 0.f;

        #pragma unroll
        for (int T = 0; T < 2; T++) {
            uint4 kb[8];
            #pragma unroll
            for (int nt = 0; nt < 8; nt++)
                kb[nt] = *(const uint4*)&Ks2[nt * 8 + g][T * 16 + 4 * j];
            #pragma unroll
            for (int nt = 0; nt < 8; nt++) {
                mma16(s[nt], qa[2*T][0], qa[2*T][1], qa[2*T][2], qa[2*T][3],
                      kb[nt].x, kb[nt].y);
                mma16(s[nt], qa[2*T+1][0], qa[2*T+1][1], qa[2*T+1][2], qa[2*T+1][3],
                      kb[nt].z, kb[nt].w);
            }
        }

        // --- online softmax (log2 domain); P stays in registers ---
        float r0 = -1e30f, r1 = -1e30f;
        #pragma unroll
        for (int nt = 0; nt < 8; nt++) {
            r0 = fmaxf(r0, fmaxf(s[nt][0], s[nt][1]));
            r1 = fmaxf(r1, fmaxf(s[nt][2], s[nt][3]));
        }
        r0 = fmaxf(r0, __shfl_xor_sync(0xffffffffu, r0, 1));
        r0 = fmaxf(r0, __shfl_xor_sync(0xffffffffu, r0, 2));
        r1 = fmaxf(r1, __shfl_xor_sync(0xffffffffu, r1, 1));
        r1 = fmaxf(r1, __shfl_xor_sync(0xffffffffu, r1, 2));
        float mn0 = fmaxf(m0, r0), mn1 = fmaxf(m1, r1);
        float sc0 = ex2f_fast(m0 - mn0), sc1 = ex2f_fast(m1 - mn1);
        unsigned pa0[8], pa1[8];
        float rs0 = 0.f, rs1 = 0.f;
        #pragma unroll
        for (int nt = 0; nt < 8; nt++) {
            float p0 = ex2f_fast(s[nt][0] - mn0);
            float p1 = ex2f_fast(s[nt][1] - mn0);
            float p2 = ex2f_fast(s[nt][2] - mn1);
            float p3 = ex2f_fast(s[nt][3] - mn1);
            rs0 += p0 + p1; rs1 += p2 + p3;
            pa0[nt] = packh2(p0, p1);     // row g:   toks nt*8+2j, +1
            pa1[nt] = packh2(p2, p3);     // row g+8
            o[nt][0] *= sc0; o[nt][1] *= sc0;
            o[nt][2] *= sc1; o[nt][3] *= sc1;
        }
        rs0 += __shfl_xor_sync(0xffffffffu, rs0, 1);
        rs0 += __shfl_xor_sync(0xffffffffu, rs0, 2);
        rs1 += __shfl_xor_sync(0xffffffffu, rs1, 1);
        rs1 += __shfl_xor_sync(0xffffffffu, rs1, 2);
        l0 = l0 * sc0 + rs0; m0 = mn0;
        l1 = l1 * sc1 + rs1; m1 = mn1;

        // --- O += P * V (A-frags directly from score/softmax registers) ---
        #pragma unroll
        for (int T = 0; T < 2; T++) {
            uint4 vb[8];
            #pragma unroll
            for (int nt = 0; nt < 8; nt++)
                vb[nt] = *(const uint4*)&Vs2[nt * 8 + g][T * 16 + 4 * j];
            #pragma unroll
            for (int nt = 0; nt < 8; nt++) {
                mma16(o[nt], pa0[4*T],   pa1[4*T],   pa0[4*T+1], pa1[4*T+1],
                      vb[nt].x, vb[nt].y);
                mma16(o[nt], pa0[4*T+2], pa1[4*T+2], pa0[4*T+3], pa1[4*T+3],
                      vb[nt].z, vb[nt].w);
            }
        }
        __syncthreads();   // protect K/V smem before next chunk overwrites
    }

    // --- normalize + store ---
    float inv0 = 1.f / l0, inv1 = 1.f / l1;
    size_t row = (size_t)(b * S + q0 + g);
    #pragma unroll
    for (int nt = 0; nt < 8; nt++) {
        int col = h * HD + nt * 8 + 2 * j;
        *(float2*)&ctx[row * EMB + col]       = make_float2(o[nt][0] * inv0, o[nt][1] * inv0);
        *(float2*)&ctx[(row + 8) * EMB + col] = make_float2(o[nt][2] * inv1, o[nt][3] * inv1);
    }
}

// ---------------------------------------------------------------------------
extern "C" void kernel_launch(void* const* d_in, const int* in_sizes, int n_in,
                              void* d_out, int out_size)
{
    const float* query = (const float*)d_in[0];
    const float* key   = (const float*)d_in[1];
    const float* value = (const float*)d_in[2];
    const float* Wq    = (const float*)d_in[3];
    const float* Wk    = (const float*)d_in[4];
    const float* Wv    = (const float*)d_in[5];
    const float* Wo    = (const float*)d_in[6];
    float* out = (float*)d_out;

    float *gQ, *gK, *gV, *gC;
    cudaGetSymbolAddress((void**)&gQ, g_Q);
    cudaGetSymbolAddress((void**)&gK, g_K);
    cudaGetSymbolAddress((void**)&gV, g_V);
    cudaGetSymbolAddress((void**)&gC, g_C);

    // Q projection
    gemm_f16<<<dim3(EMB / 128, M_ROWS / 128, 1), 256>>>(
        query, query, Wq, Wq, gQ, gQ, M_ROWS, EMB, EMB);
    // K and V projections fused in one launch (z=0: key@Wk, z=1: value@Wv)
    gemm_f16<<<dim3(KV_DIM / 128, M_ROWS / 128, 2), 256>>>(
        key, value, Wk, Wv, gK, gV, M_ROWS, KV_DIM, EMB);

    // Attention (fp16 tensor cores, flash, GQA-shared K/V, register P)
    attn_f16<<<dim3(S / 32, NKV, B), 256>>>(gQ, gK, gV, gC);

    // Output projection
    gemm_f16<<<dim3(EMB / 128, M_ROWS / 128, 1), 256>>>(
        gC, gC, Wo, Wo, out, out, M_ROWS, EMB, EMB);
}

// round 9
// speedup vs baseline: 3.2304x; 1.8586x over previous
#include <cuda_runtime.h>
#include <cuda_fp16.h>
#include <math.h>

// Problem constants
#define B 2
#define S 2048
#define EMB 2048
#define NH 32
#define NKV 8
#define HD 64
#define KV_DIM (NKV * HD)   // 512
#define M_ROWS (B * S)      // 4096

#define QSCALE (0.125f * 1.4426950408889634f)

// Scratch (device globals; no allocation allowed). All half.
__device__ __half h_Xq[M_ROWS * EMB];     // inputs converted to fp16
__device__ __half h_Xk[M_ROWS * EMB];
__device__ __half h_Xv[M_ROWS * EMB];
__device__ __half h_Wq[EMB * EMB];        // weights transposed [N][K], fp16
__device__ __half h_Wk[KV_DIM * EMB];
__device__ __half h_Wv[KV_DIM * EMB];
__device__ __half h_Wo[EMB * EMB];
__device__ __half h_Q[M_ROWS * EMB];      // Q projection (pre-scaled)
__device__ __half h_K[M_ROWS * KV_DIM];
__device__ __half h_V[M_ROWS * KV_DIM];
__device__ __half h_Ctx[M_ROWS * EMB];    // attention context

// ---------------------------------------------------------------------------
// Helpers
// ---------------------------------------------------------------------------
__device__ __forceinline__ unsigned packh2(float a, float b) {
    __half2 h = __floats2half2_rn(a, b);
    return *reinterpret_cast<unsigned*>(&h);
}
__device__ __forceinline__ unsigned h2u(__half2 h) {
    return *reinterpret_cast<unsigned*>(&h);
}
__device__ __forceinline__ float ex2f_fast(float x) {
    float r; asm("ex2.approx.f32 %0, %1;" : "=f"(r) : "f"(x)); return r;
}
// D += A(16x16,row) * B(16x8,col), fp16 inputs, f32 accum
__device__ __forceinline__ void mma16(float* c, unsigned a0, unsigned a1,
                                      unsigned a2, unsigned a3,
                                      unsigned b0, unsigned b1) {
    asm volatile(
        "mma.sync.aligned.m16n8k16.row.col.f32.f16.f16.f32 "
        "{%0,%1,%2,%3}, {%4,%5,%6,%7}, {%8,%9}, {%0,%1,%2,%3};"
        : "+f"(c[0]), "+f"(c[1]), "+f"(c[2]), "+f"(c[3])
        : "r"(a0), "r"(a1), "r"(a2), "r"(a3), "r"(b0), "r"(b1));
}
__device__ __forceinline__ void ldm_x4(unsigned* r, unsigned addr) {
    asm volatile("ldmatrix.sync.aligned.m8n8.x4.shared.b16 {%0,%1,%2,%3}, [%4];"
                 : "=r"(r[0]), "=r"(r[1]), "=r"(r[2]), "=r"(r[3]) : "r"(addr));
}
__device__ __forceinline__ void cpa16(unsigned s, const void* g) {
    asm volatile("cp.async.cg.shared.global [%0], [%1], 16;" :: "r"(s), "l"(g) : "memory");
}

// ---------------------------------------------------------------------------
// Precompute: fp32 -> fp16 input copies (query/key/value picked by blockIdx.z)
// ---------------------------------------------------------------------------
__global__ void __launch_bounds__(256)
cvt_x(const float* __restrict__ x0, const float* __restrict__ x1,
      const float* __restrict__ x2,
      __half* __restrict__ y0, __half* __restrict__ y1, __half* __restrict__ y2)
{
    const float* x = (blockIdx.z == 0) ? x0 : (blockIdx.z == 1) ? x1 : x2;
    __half*      y = (blockIdx.z == 0) ? y0 : (blockIdx.z == 1) ? y1 : y2;
    size_t i = ((size_t)blockIdx.x * 256 + threadIdx.x) * 8;
    float4 v0 = *(const float4*)&x[i];
    float4 v1 = *(const float4*)&x[i + 4];
    uint4 u;
    u.x = packh2(v0.x, v0.y); u.y = packh2(v0.z, v0.w);
    u.z = packh2(v1.x, v1.y); u.w = packh2(v1.z, v1.w);
    *(uint4*)&y[i] = u;
}

// ---------------------------------------------------------------------------
// Precompute: W [K=2048][N] fp32  ->  Wt [N][2048] fp16 (transposed)
// 64x64 tiles, 256 threads.
// ---------------------------------------------------------------------------
__global__ void __launch_bounds__(256)
cvt_wT(const float* __restrict__ W, __half* __restrict__ Wt, int N)
{
    __shared__ __half T[64][72];
    const int tid = threadIdx.x;
    const int n0 = blockIdx.x * 64, k0 = blockIdx.y * 64;
    #pragma unroll
    for (int s = 0; s < 4; s++) {
        int i  = s * 256 + tid;       // 0..1023
        int kr = i >> 4;              // 0..63
        int c4 = (i & 15) * 4;        // n offset
        float4 v = *(const float4*)&W[(size_t)(k0 + kr) * N + n0 + c4];
        T[c4 + 0][kr] = __float2half(v.x);
        T[c4 + 1][kr] = __float2half(v.y);
        T[c4 + 2][kr] = __float2half(v.z);
        T[c4 + 3][kr] = __float2half(v.w);
    }
    __syncthreads();
    #pragma unroll
    for (int s = 0; s < 2; s++) {
        int i  = s * 256 + tid;       // 0..511
        int nr = i >> 3;              // 0..63
        int c8 = i & 7;               // k chunk of 8
        uint4 u = *(const uint4*)&T[nr][c8 * 8];
        *(uint4*)&Wt[(size_t)(n0 + nr) * EMB + k0 + c8 * 8] = u;
    }
}

// ---------------------------------------------------------------------------
// fp16 GEMM, cp.async + ldmatrix.  C[M,N] = A[M,K] * Wt[N,K]^T.
// 128x128 block tile, BK=32, 128 threads (4 warps, 2x2, 64x64 per warp),
// 3-stage cp.async pipeline.  Smem rows = 32 halves (64B = 4 chunks of 16B),
// physical chunk = chunk ^ ((row>>1)&3)  ->  ldmatrix conflict-free.
// blockIdx.z selects (A0,W0,C0) / (A1,W1,C1) so K+V projections fuse.
// HALF_OUT: write half (scaled by oscale); else fp32.
// ---------------------------------------------------------------------------
template<bool HALF_OUT>
__global__ void __launch_bounds__(128)
gemm_h(const __half* __restrict__ A0, const __half* __restrict__ A1,
       const __half* __restrict__ W0, const __half* __restrict__ W1,
       void* C0v, void* C1v, int M, int N, int K, float oscale)
{
    __shared__ __align__(16) __half smA[3][128 * 32];
    __shared__ __align__(16) __half smB[3][128 * 32];

    const __half* A = blockIdx.z ? A1 : A0;
    const __half* W = blockIdx.z ? W1 : W0;
    void* Cv        = blockIdx.z ? C1v : C0v;

    const int tid  = threadIdx.x;
    const int lane = tid & 31;
    const int warp = tid >> 5;
    const int wm = warp >> 1, wn = warp & 1;
    const int g = lane >> 2, j = lane & 3;
    const int bm = blockIdx.y * 128, bn = blockIdx.x * 128;

    const unsigned sA = (unsigned)__cvta_generic_to_shared(&smA[0][0]);
    const unsigned sB = (unsigned)__cvta_generic_to_shared(&smB[0][0]);

    // loader: per stage, thread covers 4 A + 4 B 16B-chunks
    const int lc   = tid & 3;                 // chunk 0..3
    const int lr0  = tid >> 2;                // row base 0..31 (+32*s)

    auto issue = [&](int st, int k0) {
        #pragma unroll
        for (int s2 = 0; s2 < 4; s2++) {
            int row = s2 * 32 + lr0;
            int sw  = lc ^ ((row >> 1) & 3);
            unsigned so = (unsigned)(st * 8192 + row * 64 + sw * 16);
            cpa16(sA + so, A + (size_t)(bm + row) * K + k0 + lc * 8);
            cpa16(sB + so, W + (size_t)(bn + row) * K + k0 + lc * 8);
        }
        asm volatile("cp.async.commit_group;" ::: "memory");
    };

    float c[4][8][4];
    #pragma unroll
    for (int mt = 0; mt < 4; mt++)
        #pragma unroll
        for (int nt = 0; nt < 8; nt++)
            #pragma unroll
            for (int e = 0; e < 4; e++) c[mt][nt][e] = 0.f;

    const int nc = K / 32;
    issue(0, 0);
    issue(1, 32);

    // fragment lane addressing (constant per thread)
    int rowAf[4], rowBf[4];
    #pragma unroll
    for (int mt = 0; mt < 4; mt++) rowAf[mt] = wm * 64 + mt * 16 + (lane & 15);
    #pragma unroll
    for (int ntp = 0; ntp < 4; ntp++)
        rowBf[ntp] = wn * 64 + ntp * 16 + (lane & 7) + ((lane >> 4) << 3);
    const int chA = lane >> 4;          // + ks*2
    const int chB = (lane >> 3) & 1;    // + ks*2

    for (int ci = 0; ci < nc; ci++) {
        if (ci == nc - 1) asm volatile("cp.async.wait_group 0;" ::: "memory");
        else              asm volatile("cp.async.wait_group 1;" ::: "memory");
        __syncthreads();
        if (ci + 2 < nc) issue((ci + 2) % 3, (ci + 2) * 32);

        const unsigned baseA = sA + (ci % 3) * 8192;
        const unsigned baseB = sB + (ci % 3) * 8192;

        #pragma unroll
        for (int ks = 0; ks < 2; ks++) {
            unsigned af[4][4], bf[4][4];
            #pragma unroll
            for (int mt = 0; mt < 4; mt++) {
                int ch = ks * 2 + chA;
                ldm_x4(af[mt], baseA + rowAf[mt] * 64 +
                               16 * (ch ^ ((rowAf[mt] >> 1) & 3)));
            }
            #pragma unroll
            for (int ntp = 0; ntp < 4; ntp++) {
                int ch = ks * 2 + chB;
                ldm_x4(bf[ntp], baseB + rowBf[ntp] * 64 +
                                16 * (ch ^ ((rowBf[ntp] >> 1) & 3)));
            }
            #pragma unroll
            for (int mt = 0; mt < 4; mt++)
                #pragma unroll
                for (int ntp = 0; ntp < 4; ntp++) {
                    mma16(c[mt][2 * ntp],     af[mt][0], af[mt][1], af[mt][2], af[mt][3],
                          bf[ntp][0], bf[ntp][1]);
                    mma16(c[mt][2 * ntp + 1], af[mt][0], af[mt][1], af[mt][2], af[mt][3],
                          bf[ntp][2], bf[ntp][3]);
                }
        }
    }

    // epilogue
    if (HALF_OUT) {
        __half* Ch = (__half*)Cv;
        #pragma unroll
        for (int mt = 0; mt < 4; mt++) {
            int r0 = bm + wm * 64 + mt * 16 + g;
            #pragma unroll
            for (int nt = 0; nt < 8; nt++) {
                int col = bn + wn * 64 + nt * 8 + 2 * j;
                *(unsigned*)&Ch[(size_t)r0 * N + col] =
                    packh2(c[mt][nt][0] * oscale, c[mt][nt][1] * oscale);
                *(unsigned*)&Ch[(size_t)(r0 + 8) * N + col] =
                    packh2(c[mt][nt][2] * oscale, c[mt][nt][3] * oscale);
            }
        }
    } else {
        float* Cf = (float*)Cv;
        #pragma unroll
        for (int mt = 0; mt < 4; mt++) {
            int r0 = bm + wm * 64 + mt * 16 + g;
            #pragma unroll
            for (int nt = 0; nt < 8; nt++) {
                int col = bn + wn * 64 + nt * 8 + 2 * j;
                *(float2*)&Cf[(size_t)r0 * N + col] =
                    make_float2(c[mt][nt][0], c[mt][nt][1]);
                *(float2*)&Cf[(size_t)(r0 + 8) * N + col] =
                    make_float2(c[mt][nt][2], c[mt][nt][3]);
            }
        }
    }
}

// ---------------------------------------------------------------------------
// Flash attention, fp16 mma, GQA-shared K/V, P in registers, fp16 I/O.
// Block = (32 q-rows x 4 q-heads of one kv head), 256 thr, 8 warps.
// Ks2[tok][48]: half2 d-pairs slot-permuted; Vs2[d][48]: half2 tok-pairs
// slot-permuted. Stride 48 -> conflict-free uint4 fragment loads.
// ---------------------------------------------------------------------------
__device__ __forceinline__ int slotp(int w) {   // w in 0..31 (half2 index)
    return ((w >> 4) << 4) + ((w & 3) * 4) + ((w & 15) >> 2);
}

__global__ void __launch_bounds__(256, 2)
attn_f16(const __half* __restrict__ Qh, const __half* __restrict__ Kh,
         const __half* __restrict__ Vh, __half* __restrict__ ctx)
{
    __shared__ __align__(16) unsigned Ks2[64][48];
    __shared__ __align__(16) unsigned Vs2[64][48];

    const int tid  = threadIdx.x;
    const int lane = tid & 31;
    const int warp = tid >> 5;
    const int g = lane >> 2, j = lane & 3;
    const int kvh = blockIdx.y, b = blockIdx.z;
    const int h  = kvh * 4 + (warp >> 1);
    const int q0 = blockIdx.x * 32 + (warp & 1) * 16;

    // Q fragments (already scaled by QSCALE at projection time)
    unsigned qa[4][4];
    {
        const __half* qp = Qh + ((size_t)(b * S + q0 + g)) * EMB + h * HD;
        #pragma unroll
        for (int t = 0; t < 4; t++) {
            int d0 = t * 16 + 2 * j;
            qa[t][0] = *(const unsigned*)&qp[d0];
            qa[t][1] = *(const unsigned*)&qp[(size_t)8 * EMB + d0];
            qa[t][2] = *(const unsigned*)&qp[d0 + 8];
            qa[t][3] = *(const unsigned*)&qp[(size_t)8 * EMB + d0 + 8];
        }
    }

    float m0 = -1e30f, m1 = -1e30f, l0 = 0.f, l1 = 0.f;
    float o[8][4];
    #pragma unroll
    for (int nt = 0; nt < 8; nt++)
        #pragma unroll
        for (int e = 0; e < 4; e++) o[nt][e] = 0.f;

    for (int k0 = 0; k0 < S; k0 += 64) {
        // --- K loader: 64 tok x 8 chunks of 8 halves ---
        #pragma unroll
        for (int i = 0; i < 2; i++) {
            int item = i * 256 + tid;
            int tok = item >> 3, q = item & 7;
            uint4 u = *(const uint4*)&Kh[((size_t)(b * S + k0 + tok)) * KV_DIM + kvh * HD + q * 8];
            int grp = (q >> 2) * 16, qq = q & 3;
            const unsigned* w = (const unsigned*)&u;
            Ks2[tok][grp + 0 + qq]  = w[0];
            Ks2[tok][grp + 4 + qq]  = w[1];
            Ks2[tok][grp + 8 + qq]  = w[2];
            Ks2[tok][grp + 12 + qq] = w[3];
        }
        // --- V loader: 32 tok-pairs x 8 d-chunks ---
        {
            int tp = tid >> 3, dc = tid & 7;
            size_t base = ((size_t)(b * S + k0 + 2 * tp)) * KV_DIM + kvh * HD + dc * 8;
            uint4 u0 = *(const uint4*)&Vh[base];
            uint4 u1 = *(const uint4*)&Vh[base + KV_DIM];
            int sl = slotp(tp);
            const __half2* w0 = (const __half2*)&u0;
            const __half2* w1 = (const __half2*)&u1;
            #pragma unroll
            for (int e = 0; e < 4; e++) {
                Vs2[dc * 8 + 2 * e][sl]     = h2u(__lows2half2(w0[e], w1[e]));
                Vs2[dc * 8 + 2 * e + 1][sl] = h2u(__highs2half2(w0[e], w1[e]));
            }
        }
        __syncthreads();

        // --- scores: S = Q * K^T (16 x 64 per warp) ---
        float s[8][4];
        #pragma unroll
        for (int nt = 0; nt < 8; nt++)
            #pragma unroll
            for (int e = 0; e < 4; e++) s[nt][e] = 0.f;

        #pragma unroll
        for (int T = 0; T < 2; T++) {
            uint4 kb[8];
            #pragma unroll
            for (int nt = 0; nt < 8; nt++)
                kb[nt] = *(const uint4*)&Ks2[nt * 8 + g][T * 16 + 4 * j];
            #pragma unroll
            for (int nt = 0; nt < 8; nt++) {
                mma16(s[nt], qa[2*T][0], qa[2*T][1], qa[2*T][2], qa[2*T][3],
                      kb[nt].x, kb[nt].y);
                mma16(s[nt], qa[2*T+1][0], qa[2*T+1][1], qa[2*T+1][2], qa[2*T+1][3],
                      kb[nt].z, kb[nt].w);
            }
        }

        // --- online softmax (log2 domain); P stays in registers ---
        float r0 = -1e30f, r1 = -1e30f;
        #pragma unroll
        for (int nt = 0; nt < 8; nt++) {
            r0 = fmaxf(r0, fmaxf(s[nt][0], s[nt][1]));
            r1 = fmaxf(r1, fmaxf(s[nt][2], s[nt][3]));
        }
        r0 = fmaxf(r0, __shfl_xor_sync(0xffffffffu, r0, 1));
        r0 = fmaxf(r0, __shfl_xor_sync(0xffffffffu, r0, 2));
        r1 = fmaxf(r1, __shfl_xor_sync(0xffffffffu, r1, 1));
        r1 = fmaxf(r1, __shfl_xor_sync(0xffffffffu, r1, 2));
        float mn0 = fmaxf(m0, r0), mn1 = fmaxf(m1, r1);
        float sc0 = ex2f_fast(m0 - mn0), sc1 = ex2f_fast(m1 - mn1);
        unsigned pa0[8], pa1[8];
        float rs0 = 0.f, rs1 = 0.f;
        #pragma unroll
        for (int nt = 0; nt < 8; nt++) {
            float p0 = ex2f_fast(s[nt][0] - mn0);
            float p1 = ex2f_fast(s[nt][1] - mn0);
            float p2 = ex2f_fast(s[nt][2] - mn1);
            float p3 = ex2f_fast(s[nt][3] - mn1);
            rs0 += p0 + p1; rs1 += p2 + p3;
            pa0[nt] = packh2(p0, p1);
            pa1[nt] = packh2(p2, p3);
            o[nt][0] *= sc0; o[nt][1] *= sc0;
            o[nt][2] *= sc1; o[nt][3] *= sc1;
        }
        rs0 += __shfl_xor_sync(0xffffffffu, rs0, 1);
        rs0 += __shfl_xor_sync(0xffffffffu, rs0, 2);
        rs1 += __shfl_xor_sync(0xffffffffu, rs1, 1);
        rs1 += __shfl_xor_sync(0xffffffffu, rs1, 2);
        l0 = l0 * sc0 + rs0; m0 = mn0;
        l1 = l1 * sc1 + rs1; m1 = mn1;

        // --- O += P * V ---
        #pragma unroll
        for (int T = 0; T < 2; T++) {
            uint4 vb[8];
            #pragma unroll
            for (int nt = 0; nt < 8; nt++)
                vb[nt] = *(const uint4*)&Vs2[nt * 8 + g][T * 16 + 4 * j];
            #pragma unroll
            for (int nt = 0; nt < 8; nt++) {
                mma16(o[nt], pa0[4*T],   pa1[4*T],   pa0[4*T+1], pa1[4*T+1],
                      vb[nt].x, vb[nt].y);
                mma16(o[nt], pa0[4*T+2], pa1[4*T+2], pa0[4*T+3], pa1[4*T+3],
                      vb[nt].z, vb[nt].w);
            }
        }
        __syncthreads();   // protect K/V smem before next chunk overwrites
    }

    // --- normalize + store (fp16 ctx) ---
    float inv0 = 1.f / l0, inv1 = 1.f / l1;
    size_t row = (size_t)(b * S + q0 + g);
    #pragma unroll
    for (int nt = 0; nt < 8; nt++) {
        int col = h * HD + nt * 8 + 2 * j;
        *(unsigned*)&ctx[row * EMB + col] =
            packh2(o[nt][0] * inv0, o[nt][1] * inv0);
        *(unsigned*)&ctx[(row + 8) * EMB + col] =
            packh2(o[nt][2] * inv1, o[nt][3] * inv1);
    }
}

// ---------------------------------------------------------------------------
extern "C" void kernel_launch(void* const* d_in, const int* in_sizes, int n_in,
                              void* d_out, int out_size)
{
    const float* query = (const float*)d_in[0];
    const float* key   = (const float*)d_in[1];
    const float* value = (const float*)d_in[2];
    const float* Wq    = (const float*)d_in[3];
    const float* Wk    = (const float*)d_in[4];
    const float* Wv    = (const float*)d_in[5];
    const float* Wo    = (const float*)d_in[6];
    float* out = (float*)d_out;

    __half *pXq, *pXk, *pXv, *pWq, *pWk, *pWv, *pWo, *pQ, *pK, *pV, *pCtx;
    cudaGetSymbolAddress((void**)&pXq, h_Xq);
    cudaGetSymbolAddress((void**)&pXk, h_Xk);
    cudaGetSymbolAddress((void**)&pXv, h_Xv);
    cudaGetSymbolAddress((void**)&pWq, h_Wq);
    cudaGetSymbolAddress((void**)&pWk, h_Wk);
    cudaGetSymbolAddress((void**)&pWv, h_Wv);
    cudaGetSymbolAddress((void**)&pWo, h_Wo);
    cudaGetSymbolAddress((void**)&pQ,  h_Q);
    cudaGetSymbolAddress((void**)&pK,  h_K);
    cudaGetSymbolAddress((void**)&pV,  h_V);
    cudaGetSymbolAddress((void**)&pCtx, h_Ctx);

    // fp32 -> fp16 precompute (inputs + transposed weights)
    cvt_x<<<dim3(M_ROWS * EMB / 8 / 256, 1, 3), 256>>>(
        query, key, value, pXq, pXk, pXv);
    cvt_wT<<<dim3(EMB / 64,    EMB / 64), 256>>>(Wq, pWq, EMB);
    cvt_wT<<<dim3(KV_DIM / 64, EMB / 64), 256>>>(Wk, pWk, KV_DIM);
    cvt_wT<<<dim3(KV_DIM / 64, EMB / 64), 256>>>(Wv, pWv, KV_DIM);
    cvt_wT<<<dim3(EMB / 64,    EMB / 64), 256>>>(Wo, pWo, EMB);

    // Q projection (writes half, pre-scaled for softmax)
    gemm_h<true><<<dim3(EMB / 128, M_ROWS / 128, 1), 128>>>(
        pXq, pXq, pWq, pWq, pQ, pQ, M_ROWS, EMB, EMB, QSCALE);
    // K and V projections fused (z=0: key@Wk, z=1: value@Wv)
    gemm_h<true><<<dim3(KV_DIM / 128, M_ROWS / 128, 2), 128>>>(
        pXk, pXv, pWk, pWv, pK, pV, M_ROWS, KV_DIM, EMB, 1.0f);

    // Attention
    attn_f16<<<dim3(S / 32, NKV, B), 256>>>(pQ, pK, pV, pCtx);

    // Output projection (fp32 out)
    gemm_h<false><<<dim3(EMB / 128, M_ROWS / 128, 1), 128>>>(
        pCtx, pCtx, pWo, pWo, out, out, M_ROWS, EMB, EMB, 1.0f);
}

// round 10
// speedup vs baseline: 3.8262x; 1.1844x over previous
#include <cuda_runtime.h>
#include <cuda_fp16.h>
#include <math.h>

// Problem constants
#define B 2
#define S 2048
#define EMB 2048
#define NH 32
#define NKV 8
#define HD 64
#define KV_DIM (NKV * HD)   // 512
#define M_ROWS (B * S)      // 4096

#define QSCALE (0.125f * 1.4426950408889634f)

// Scratch (device globals; no allocation allowed). All half.
__device__ __half h_Xq[M_ROWS * EMB];     // inputs converted to fp16
__device__ __half h_Xk[M_ROWS * EMB];
__device__ __half h_Xv[M_ROWS * EMB];
__device__ __half h_Wq[EMB * EMB];        // weights transposed [N][K], fp16
__device__ __half h_Wk[KV_DIM * EMB];
__device__ __half h_Wv[KV_DIM * EMB];
__device__ __half h_Wo[EMB * EMB];
__device__ __half h_Q[M_ROWS * EMB];      // Q projection (pre-scaled)
__device__ __half h_K[M_ROWS * KV_DIM];
__device__ __half h_V[M_ROWS * KV_DIM];
__device__ __half h_Ctx[M_ROWS * EMB];    // attention context

// ---------------------------------------------------------------------------
// Helpers
// ---------------------------------------------------------------------------
__device__ __forceinline__ unsigned packh2(float a, float b) {
    __half2 h = __floats2half2_rn(a, b);
    return *reinterpret_cast<unsigned*>(&h);
}
__device__ __forceinline__ float ex2f_fast(float x) {
    float r; asm("ex2.approx.f32 %0, %1;" : "=f"(r) : "f"(x)); return r;
}
// D += A(16x16,row) * B(16x8,col), fp16 inputs, f32 accum
__device__ __forceinline__ void mma16(float* c, unsigned a0, unsigned a1,
                                      unsigned a2, unsigned a3,
                                      unsigned b0, unsigned b1) {
    asm volatile(
        "mma.sync.aligned.m16n8k16.row.col.f32.f16.f16.f32 "
        "{%0,%1,%2,%3}, {%4,%5,%6,%7}, {%8,%9}, {%0,%1,%2,%3};"
        : "+f"(c[0]), "+f"(c[1]), "+f"(c[2]), "+f"(c[3])
        : "r"(a0), "r"(a1), "r"(a2), "r"(a3), "r"(b0), "r"(b1));
}
__device__ __forceinline__ void ldm_x4(unsigned* r, unsigned addr) {
    asm volatile("ldmatrix.sync.aligned.m8n8.x4.shared.b16 {%0,%1,%2,%3}, [%4];"
                 : "=r"(r[0]), "=r"(r[1]), "=r"(r[2]), "=r"(r[3]) : "r"(addr));
}
__device__ __forceinline__ void ldm_x4t(unsigned* r, unsigned addr) {
    asm volatile("ldmatrix.sync.aligned.m8n8.x4.trans.shared.b16 {%0,%1,%2,%3}, [%4];"
                 : "=r"(r[0]), "=r"(r[1]), "=r"(r[2]), "=r"(r[3]) : "r"(addr));
}
__device__ __forceinline__ void cpa16(unsigned s, const void* g) {
    asm volatile("cp.async.cg.shared.global [%0], [%1], 16;" :: "r"(s), "l"(g) : "memory");
}

// ---------------------------------------------------------------------------
// Precompute: fp32 -> fp16 input copies (query/key/value picked by blockIdx.z)
// ---------------------------------------------------------------------------
__global__ void __launch_bounds__(256)
cvt_x(const float* __restrict__ x0, const float* __restrict__ x1,
      const float* __restrict__ x2,
      __half* __restrict__ y0, __half* __restrict__ y1, __half* __restrict__ y2)
{
    const float* x = (blockIdx.z == 0) ? x0 : (blockIdx.z == 1) ? x1 : x2;
    __half*      y = (blockIdx.z == 0) ? y0 : (blockIdx.z == 1) ? y1 : y2;
    size_t i = ((size_t)blockIdx.x * 256 + threadIdx.x) * 8;
    float4 v0 = *(const float4*)&x[i];
    float4 v1 = *(const float4*)&x[i + 4];
    uint4 u;
    u.x = packh2(v0.x, v0.y); u.y = packh2(v0.z, v0.w);
    u.z = packh2(v1.x, v1.y); u.w = packh2(v1.z, v1.w);
    *(uint4*)&y[i] = u;
}

// ---------------------------------------------------------------------------
// Precompute: W [K=2048][N] fp32  ->  Wt [N][2048] fp16 (transposed)
// ---------------------------------------------------------------------------
__global__ void __launch_bounds__(256)
cvt_wT(const float* __restrict__ W, __half* __restrict__ Wt, int N)
{
    __shared__ __half T[64][72];
    const int tid = threadIdx.x;
    const int n0 = blockIdx.x * 64, k0 = blockIdx.y * 64;
    #pragma unroll
    for (int s = 0; s < 4; s++) {
        int i  = s * 256 + tid;
        int kr = i >> 4;
        int c4 = (i & 15) * 4;
        float4 v = *(const float4*)&W[(size_t)(k0 + kr) * N + n0 + c4];
        T[c4 + 0][kr] = __float2half(v.x);
        T[c4 + 1][kr] = __float2half(v.y);
        T[c4 + 2][kr] = __float2half(v.z);
        T[c4 + 3][kr] = __float2half(v.w);
    }
    __syncthreads();
    #pragma unroll
    for (int s = 0; s < 2; s++) {
        int i  = s * 256 + tid;
        int nr = i >> 3;
        int c8 = i & 7;
        uint4 u = *(const uint4*)&T[nr][c8 * 8];
        *(uint4*)&Wt[(size_t)(n0 + nr) * EMB + k0 + c8 * 8] = u;
    }
}

// ---------------------------------------------------------------------------
// fp16 GEMM, cp.async + ldmatrix.  C[M,N] = A[M,K] * Wt[N,K]^T.
// 128x128 block tile, BK=32, 128 threads (4 warps, 2x2, 64x64 per warp),
// 3-stage cp.async pipeline, XOR-swizzled smem, ldmatrix fragments.
// blockIdx.z selects (A0,W0,C0) / (A1,W1,C1) so K+V projections fuse.
// ---------------------------------------------------------------------------
template<bool HALF_OUT>
__global__ void __launch_bounds__(128)
gemm_h(const __half* __restrict__ A0, const __half* __restrict__ A1,
       const __half* __restrict__ W0, const __half* __restrict__ W1,
       void* C0v, void* C1v, int M, int N, int K, float oscale)
{
    __shared__ __align__(16) __half smA[3][128 * 32];
    __shared__ __align__(16) __half smB[3][128 * 32];

    const __half* A = blockIdx.z ? A1 : A0;
    const __half* W = blockIdx.z ? W1 : W0;
    void* Cv        = blockIdx.z ? C1v : C0v;

    const int tid  = threadIdx.x;
    const int lane = tid & 31;
    const int warp = tid >> 5;
    const int wm = warp >> 1, wn = warp & 1;
    const int g = lane >> 2, j = lane & 3;
    const int bm = blockIdx.y * 128, bn = blockIdx.x * 128;

    const unsigned sA = (unsigned)__cvta_generic_to_shared(&smA[0][0]);
    const unsigned sB = (unsigned)__cvta_generic_to_shared(&smB[0][0]);

    const int lc  = tid & 3;
    const int lr0 = tid >> 2;

    auto issue = [&](int st, int k0) {
        #pragma unroll
        for (int s2 = 0; s2 < 4; s2++) {
            int row = s2 * 32 + lr0;
            int sw  = lc ^ ((row >> 1) & 3);
            unsigned so = (unsigned)(st * 8192 + row * 64 + sw * 16);
            cpa16(sA + so, A + (size_t)(bm + row) * K + k0 + lc * 8);
            cpa16(sB + so, W + (size_t)(bn + row) * K + k0 + lc * 8);
        }
        asm volatile("cp.async.commit_group;" ::: "memory");
    };

    float c[4][8][4];
    #pragma unroll
    for (int mt = 0; mt < 4; mt++)
        #pragma unroll
        for (int nt = 0; nt < 8; nt++)
            #pragma unroll
            for (int e = 0; e < 4; e++) c[mt][nt][e] = 0.f;

    const int nc = K / 32;
    issue(0, 0);
    issue(1, 32);

    int rowAf[4], rowBf[4];
    #pragma unroll
    for (int mt = 0; mt < 4; mt++) rowAf[mt] = wm * 64 + mt * 16 + (lane & 15);
    #pragma unroll
    for (int ntp = 0; ntp < 4; ntp++)
        rowBf[ntp] = wn * 64 + ntp * 16 + (lane & 7) + ((lane >> 4) << 3);
    const int chA = lane >> 4;
    const int chB = (lane >> 3) & 1;

    for (int ci = 0; ci < nc; ci++) {
        if (ci == nc - 1) asm volatile("cp.async.wait_group 0;" ::: "memory");
        else              asm volatile("cp.async.wait_group 1;" ::: "memory");
        __syncthreads();
        if (ci + 2 < nc) issue((ci + 2) % 3, (ci + 2) * 32);

        const unsigned baseA = sA + (ci % 3) * 8192;
        const unsigned baseB = sB + (ci % 3) * 8192;

        #pragma unroll
        for (int ks = 0; ks < 2; ks++) {
            unsigned af[4][4], bf[4][4];
            #pragma unroll
            for (int mt = 0; mt < 4; mt++) {
                int ch = ks * 2 + chA;
                ldm_x4(af[mt], baseA + rowAf[mt] * 64 +
                               16 * (ch ^ ((rowAf[mt] >> 1) & 3)));
            }
            #pragma unroll
            for (int ntp = 0; ntp < 4; ntp++) {
                int ch = ks * 2 + chB;
                ldm_x4(bf[ntp], baseB + rowBf[ntp] * 64 +
                                16 * (ch ^ ((rowBf[ntp] >> 1) & 3)));
            }
            #pragma unroll
            for (int mt = 0; mt < 4; mt++)
                #pragma unroll
                for (int ntp = 0; ntp < 4; ntp++) {
                    mma16(c[mt][2 * ntp],     af[mt][0], af[mt][1], af[mt][2], af[mt][3],
                          bf[ntp][0], bf[ntp][1]);
                    mma16(c[mt][2 * ntp + 1], af[mt][0], af[mt][1], af[mt][2], af[mt][3],
                          bf[ntp][2], bf[ntp][3]);
                }
        }
    }

    if (HALF_OUT) {
        __half* Ch = (__half*)Cv;
        #pragma unroll
        for (int mt = 0; mt < 4; mt++) {
            int r0 = bm + wm * 64 + mt * 16 + g;
            #pragma unroll
            for (int nt = 0; nt < 8; nt++) {
                int col = bn + wn * 64 + nt * 8 + 2 * j;
                *(unsigned*)&Ch[(size_t)r0 * N + col] =
                    packh2(c[mt][nt][0] * oscale, c[mt][nt][1] * oscale);
                *(unsigned*)&Ch[(size_t)(r0 + 8) * N + col] =
                    packh2(c[mt][nt][2] * oscale, c[mt][nt][3] * oscale);
            }
        }
    } else {
        float* Cf = (float*)Cv;
        #pragma unroll
        for (int mt = 0; mt < 4; mt++) {
            int r0 = bm + wm * 64 + mt * 16 + g;
            #pragma unroll
            for (int nt = 0; nt < 8; nt++) {
                int col = bn + wn * 64 + nt * 8 + 2 * j;
                *(float2*)&Cf[(size_t)r0 * N + col] =
                    make_float2(c[mt][nt][0], c[mt][nt][1]);
                *(float2*)&Cf[(size_t)(r0 + 8) * N + col] =
                    make_float2(c[mt][nt][2], c[mt][nt][3]);
            }
        }
    }
}

// ---------------------------------------------------------------------------
// Flash attention, fp16 mma, GQA-shared K/V, P in registers.
// Block = (32 q-rows x 4 q-heads of one kv head), 256 thr, 8 warps.
// K and V tiles stored RAW [64 tok][64 half], XOR-swizzled (chunk ^= tok&7),
// filled by 3-stage cp.async pipeline. Score B-frags via ldmatrix (rows=tok,
// chunks along d); PV B-frags via ldmatrix.trans (HW transpose). MMA order
// identical to previous round -> bitwise-identical results.
// ---------------------------------------------------------------------------
__global__ void __launch_bounds__(256, 2)
attn_f16(const __half* __restrict__ Qh, const __half* __restrict__ Kh,
         const __half* __restrict__ Vh, __half* __restrict__ ctx)
{
    __shared__ __align__(16) __half Kb[3][64 * 64];
    __shared__ __align__(16) __half Vb[3][64 * 64];

    const int tid  = threadIdx.x;
    const int lane = tid & 31;
    const int warp = tid >> 5;
    const int g = lane >> 2, j = lane & 3;
    const int kvh = blockIdx.y, b = blockIdx.z;
    const int h  = kvh * 4 + (warp >> 1);
    const int q0 = blockIdx.x * 32 + (warp & 1) * 16;

    const unsigned sK = (unsigned)__cvta_generic_to_shared(&Kb[0][0]);
    const unsigned sV = (unsigned)__cvta_generic_to_shared(&Vb[0][0]);

    const __half* kbase = Kh + ((size_t)b * S) * KV_DIM + kvh * HD;
    const __half* vbase = Vh + ((size_t)b * S) * KV_DIM + kvh * HD;

    auto issue = [&](int st, int tk0) {
        #pragma unroll
        for (int i = 0; i < 2; i++) {
            int it  = i * 256 + tid;
            int tok = it >> 3, ch = it & 7;
            unsigned off = (unsigned)(st * 8192 + tok * 128 + 16 * (ch ^ (tok & 7)));
            size_t go = (size_t)(tk0 + tok) * KV_DIM + ch * 8;
            cpa16(sK + off, kbase + go);
            cpa16(sV + off, vbase + go);
        }
        asm volatile("cp.async.commit_group;" ::: "memory");
    };

    // Q fragments (already scaled by QSCALE at projection time)
    unsigned qa[4][4];
    {
        const __half* qp = Qh + ((size_t)(b * S + q0 + g)) * EMB + h * HD;
        #pragma unroll
        for (int t = 0; t < 4; t++) {
            int d0 = t * 16 + 2 * j;
            qa[t][0] = *(const unsigned*)&qp[d0];
            qa[t][1] = *(const unsigned*)&qp[(size_t)8 * EMB + d0];
            qa[t][2] = *(const unsigned*)&qp[d0 + 8];
            qa[t][3] = *(const unsigned*)&qp[(size_t)8 * EMB + d0 + 8];
        }
    }

    float m0 = -1e30f, m1 = -1e30f, l0 = 0.f, l1 = 0.f;
    float o[8][4];
    #pragma unroll
    for (int nt = 0; nt < 8; nt++)
        #pragma unroll
        for (int e = 0; e < 4; e++) o[nt][e] = 0.f;

    // fragment addresses (constant per thread)
    const int rowKf = (lane & 7) + ((lane >> 4) << 3);    // + ntp*16
    const int chKf  = (lane >> 3) & 1;                    // + ks*2
    const int rowVf = lane & 15;                          // + ks*16
    const int chVf  = lane >> 4;                          // + ntp*2

    const int nc = S / 64;    // 32 chunks
    issue(0, 0);
    issue(1, 64);

    for (int ci = 0; ci < nc; ci++) {
        if (ci == nc - 1) asm volatile("cp.async.wait_group 0;" ::: "memory");
        else              asm volatile("cp.async.wait_group 1;" ::: "memory");
        __syncthreads();
        if (ci + 2 < nc) issue((ci + 2) % 3, (ci + 2) * 64);

        const unsigned baseK = sK + (ci % 3) * 8192;
        const unsigned baseV = sV + (ci % 3) * 8192;

        // --- scores: S = Q * K^T (16 x 64 per warp) ---
        float s[8][4];
        #pragma unroll
        for (int nt = 0; nt < 8; nt++)
            #pragma unroll
            for (int e = 0; e < 4; e++) s[nt][e] = 0.f;

        #pragma unroll
        for (int ks = 0; ks < 4; ks++) {
            #pragma unroll
            for (int ntp = 0; ntp < 4; ntp++) {
                unsigned kb[4];
                int row = ntp * 16 + rowKf;
                int ch  = ks * 2 + chKf;
                ldm_x4(kb, baseK + row * 128 + 16 * (ch ^ (row & 7)));
                mma16(s[2 * ntp],     qa[ks][0], qa[ks][1], qa[ks][2], qa[ks][3],
                      kb[0], kb[1]);
                mma16(s[2 * ntp + 1], qa[ks][0], qa[ks][1], qa[ks][2], qa[ks][3],
                      kb[2], kb[3]);
            }
        }

        // --- online softmax (log2 domain); P stays in registers ---
        float r0 = -1e30f, r1 = -1e30f;
        #pragma unroll
        for (int nt = 0; nt < 8; nt++) {
            r0 = fmaxf(r0, fmaxf(s[nt][0], s[nt][1]));
            r1 = fmaxf(r1, fmaxf(s[nt][2], s[nt][3]));
        }
        r0 = fmaxf(r0, __shfl_xor_sync(0xffffffffu, r0, 1));
        r0 = fmaxf(r0, __shfl_xor_sync(0xffffffffu, r0, 2));
        r1 = fmaxf(r1, __shfl_xor_sync(0xffffffffu, r1, 1));
        r1 = fmaxf(r1, __shfl_xor_sync(0xffffffffu, r1, 2));
        float mn0 = fmaxf(m0, r0), mn1 = fmaxf(m1, r1);
        float sc0 = ex2f_fast(m0 - mn0), sc1 = ex2f_fast(m1 - mn1);
        unsigned pa0[8], pa1[8];
        float rs0 = 0.f, rs1 = 0.f;
        #pragma unroll
        for (int nt = 0; nt < 8; nt++) {
            float p0 = ex2f_fast(s[nt][0] - mn0);
            float p1 = ex2f_fast(s[nt][1] - mn0);
            float p2 = ex2f_fast(s[nt][2] - mn1);
            float p3 = ex2f_fast(s[nt][3] - mn1);
            rs0 += p0 + p1; rs1 += p2 + p3;
            pa0[nt] = packh2(p0, p1);
            pa1[nt] = packh2(p2, p3);
            o[nt][0] *= sc0; o[nt][1] *= sc0;
            o[nt][2] *= sc1; o[nt][3] *= sc1;
        }
        rs0 += __shfl_xor_sync(0xffffffffu, rs0, 1);
        rs0 += __shfl_xor_sync(0xffffffffu, rs0, 2);
        rs1 += __shfl_xor_sync(0xffffffffu, rs1, 1);
        rs1 += __shfl_xor_sync(0xffffffffu, rs1, 2);
        l0 = l0 * sc0 + rs0; m0 = mn0;
        l1 = l1 * sc1 + rs1; m1 = mn1;

        // --- O += P * V (V B-frags via ldmatrix.trans on raw rows) ---
        #pragma unroll
        for (int ks = 0; ks < 4; ks++) {
            #pragma unroll
            for (int ntp = 0; ntp < 4; ntp++) {
                unsigned vb[4];
                int row = ks * 16 + rowVf;
                int ch  = ntp * 2 + chVf;
                ldm_x4t(vb, baseV + row * 128 + 16 * (ch ^ (row & 7)));
                mma16(o[2 * ntp],     pa0[2 * ks], pa1[2 * ks],
                      pa0[2 * ks + 1], pa1[2 * ks + 1], vb[0], vb[1]);
                mma16(o[2 * ntp + 1], pa0[2 * ks], pa1[2 * ks],
                      pa0[2 * ks + 1], pa1[2 * ks + 1], vb[2], vb[3]);
            }
        }
    }

    // --- normalize + store (fp16 ctx) ---
    float inv0 = 1.f / l0, inv1 = 1.f / l1;
    size_t row = (size_t)(b * S + q0 + g);
    #pragma unroll
    for (int nt = 0; nt < 8; nt++) {
        int col = h * HD + nt * 8 + 2 * j;
        *(unsigned*)&ctx[row * EMB + col] =
            packh2(o[nt][0] * inv0, o[nt][1] * inv0);
        *(unsigned*)&ctx[(row + 8) * EMB + col] =
            packh2(o[nt][2] * inv1, o[nt][3] * inv1);
    }
}

// ---------------------------------------------------------------------------
extern "C" void kernel_launch(void* const* d_in, const int* in_sizes, int n_in,
                              void* d_out, int out_size)
{
    const float* query = (const float*)d_in[0];
    const float* key   = (const float*)d_in[1];
    const float* value = (const float*)d_in[2];
    const float* Wq    = (const float*)d_in[3];
    const float* Wk    = (const float*)d_in[4];
    const float* Wv    = (const float*)d_in[5];
    const float* Wo    = (const float*)d_in[6];
    float* out = (float*)d_out;

    __half *pXq, *pXk, *pXv, *pWq, *pWk, *pWv, *pWo, *pQ, *pK, *pV, *pCtx;
    cudaGetSymbolAddress((void**)&pXq, h_Xq);
    cudaGetSymbolAddress((void**)&pXk, h_Xk);
    cudaGetSymbolAddress((void**)&pXv, h_Xv);
    cudaGetSymbolAddress((void**)&pWq, h_Wq);
    cudaGetSymbolAddress((void**)&pWk, h_Wk);
    cudaGetSymbolAddress((void**)&pWv, h_Wv);
    cudaGetSymbolAddress((void**)&pWo, h_Wo);
    cudaGetSymbolAddress((void**)&pQ,  h_Q);
    cudaGetSymbolAddress((void**)&pK,  h_K);
    cudaGetSymbolAddress((void**)&pV,  h_V);
    cudaGetSymbolAddress((void**)&pCtx, h_Ctx);

    // fp32 -> fp16 precompute (inputs + transposed weights)
    cvt_x<<<dim3(M_ROWS * EMB / 8 / 256, 1, 3), 256>>>(
        query, key, value, pXq, pXk, pXv);
    cvt_wT<<<dim3(EMB / 64,    EMB / 64), 256>>>(Wq, pWq, EMB);
    cvt_wT<<<dim3(KV_DIM / 64, EMB / 64), 256>>>(Wk, pWk, KV_DIM);
    cvt_wT<<<dim3(KV_DIM / 64, EMB / 64), 256>>>(Wv, pWv, KV_DIM);
    cvt_wT<<<dim3(EMB / 64,    EMB / 64), 256>>>(Wo, pWo, EMB);

    // Q projection (writes half, pre-scaled for softmax)
    gemm_h<true><<<dim3(EMB / 128, M_ROWS / 128, 1), 128>>>(
        pXq, pXq, pWq, pWq, pQ, pQ, M_ROWS, EMB, EMB, QSCALE);
    // K and V projections fused (z=0: key@Wk, z=1: value@Wv)
    gemm_h<true><<<dim3(KV_DIM / 128, M_ROWS / 128, 2), 128>>>(
        pXk, pXv, pWk, pWv, pK, pV, M_ROWS, KV_DIM, EMB, 1.0f);

    // Attention (cp.async-pipelined K/V, ldmatrix/.trans fragments)
    attn_f16<<<dim3(S / 32, NKV, B), 256>>>(pQ, pK, pV, pCtx);

    // Output projection (fp32 out)
    gemm_h<false><<<dim3(EMB / 128, M_ROWS / 128, 1), 128>>>(
        pCtx, pCtx, pWo, pWo, out, out, M_ROWS, EMB, EMB, 1.0f);
}

// round 13
// speedup vs baseline: 4.0759x; 1.0653x over previous
#include <cuda_runtime.h>
#include <cuda_fp16.h>
#include <math.h>

// Problem constants
#define B 2
#define S 2048
#define EMB 2048
#define NH 32
#define NKV 8
#define HD 64
#define KV_DIM (NKV * HD)   // 512
#define M_ROWS (B * S)      // 4096

#define QSCALE (0.125f * 1.4426950408889634f)

// Scratch (device globals; no allocation allowed). All half.
__device__ __half h_Xq[M_ROWS * EMB];     // inputs converted to fp16
__device__ __half h_Xk[M_ROWS * EMB];
__device__ __half h_Xv[M_ROWS * EMB];
__device__ __half h_Wq[EMB * EMB];        // weights transposed [N][K], fp16
__device__ __half h_Wk[KV_DIM * EMB];
__device__ __half h_Wv[KV_DIM * EMB];
__device__ __half h_Wo[EMB * EMB];
__device__ __half h_Q[M_ROWS * EMB];      // Q projection (pre-scaled)
__device__ __half h_K[M_ROWS * KV_DIM];
__device__ __half h_V[M_ROWS * KV_DIM];
__device__ __half h_Ctx[M_ROWS * EMB];    // attention context

// ---------------------------------------------------------------------------
// Helpers
// ---------------------------------------------------------------------------
__device__ __forceinline__ unsigned packh2(float a, float b) {
    __half2 h = __floats2half2_rn(a, b);
    return *reinterpret_cast<unsigned*>(&h);
}
__device__ __forceinline__ float ex2f_fast(float x) {
    float r; asm("ex2.approx.f32 %0, %1;" : "=f"(r) : "f"(x)); return r;
}
// D += A(16x16,row) * B(16x8,col), fp16 inputs, f32 accum
__device__ __forceinline__ void mma16(float* c, unsigned a0, unsigned a1,
                                      unsigned a2, unsigned a3,
                                      unsigned b0, unsigned b1) {
    asm volatile(
        "mma.sync.aligned.m16n8k16.row.col.f32.f16.f16.f32 "
        "{%0,%1,%2,%3}, {%4,%5,%6,%7}, {%8,%9}, {%0,%1,%2,%3};"
        : "+f"(c[0]), "+f"(c[1]), "+f"(c[2]), "+f"(c[3])
        : "r"(a0), "r"(a1), "r"(a2), "r"(a3), "r"(b0), "r"(b1));
}
__device__ __forceinline__ void ldm_x4(unsigned* r, unsigned addr) {
    asm volatile("ldmatrix.sync.aligned.m8n8.x4.shared.b16 {%0,%1,%2,%3}, [%4];"
                 : "=r"(r[0]), "=r"(r[1]), "=r"(r[2]), "=r"(r[3]) : "r"(addr));
}
__device__ __forceinline__ void ldm_x4t(unsigned* r, unsigned addr) {
    asm volatile("ldmatrix.sync.aligned.m8n8.x4.trans.shared.b16 {%0,%1,%2,%3}, [%4];"
                 : "=r"(r[0]), "=r"(r[1]), "=r"(r[2]), "=r"(r[3]) : "r"(addr));
}
__device__ __forceinline__ void cpa16(unsigned s, const void* g) {
    asm volatile("cp.async.cg.shared.global [%0], [%1], 16;" :: "r"(s), "l"(g) : "memory");
}

// ---------------------------------------------------------------------------
// Precompute: fp32 -> fp16 input copies (query/key/value picked by blockIdx.z)
// ---------------------------------------------------------------------------
__global__ void __launch_bounds__(256)
cvt_x(const float* __restrict__ x0, const float* __restrict__ x1,
      const float* __restrict__ x2,
      __half* __restrict__ y0, __half* __restrict__ y1, __half* __restrict__ y2)
{
    const float* x = (blockIdx.z == 0) ? x0 : (blockIdx.z == 1) ? x1 : x2;
    __half*      y = (blockIdx.z == 0) ? y0 : (blockIdx.z == 1) ? y1 : y2;
    size_t i = ((size_t)blockIdx.x * 256 + threadIdx.x) * 8;
    float4 v0 = *(const float4*)&x[i];
    float4 v1 = *(const float4*)&x[i + 4];
    uint4 u;
    u.x = packh2(v0.x, v0.y); u.y = packh2(v0.z, v0.w);
    u.z = packh2(v1.x, v1.y); u.w = packh2(v1.z, v1.w);
    *(uint4*)&y[i] = u;
}

// ---------------------------------------------------------------------------
// Precompute: W [K=2048][N] fp32 -> Wt [N][2048] fp16 (transposed).
// blockIdx.z selects (W0->T0) or (W1->T1); both shapes share N.
// ---------------------------------------------------------------------------
__global__ void __launch_bounds__(256)
cvt_wT(const float* __restrict__ W0, const float* __restrict__ W1,
       __half* __restrict__ T0, __half* __restrict__ T1, int N)
{
    const float* W = blockIdx.z ? W1 : W0;
    __half*     Wt = blockIdx.z ? T1 : T0;
    __shared__ __half T[64][72];
    const int tid = threadIdx.x;
    const int n0 = blockIdx.x * 64, k0 = blockIdx.y * 64;
    #pragma unroll
    for (int s = 0; s < 4; s++) {
        int i  = s * 256 + tid;
        int kr = i >> 4;
        int c4 = (i & 15) * 4;
        float4 v = *(const float4*)&W[(size_t)(k0 + kr) * N + n0 + c4];
        T[c4 + 0][kr] = __float2half(v.x);
        T[c4 + 1][kr] = __float2half(v.y);
        T[c4 + 2][kr] = __float2half(v.z);
        T[c4 + 3][kr] = __float2half(v.w);
    }
    __syncthreads();
    #pragma unroll
    for (int s = 0; s < 2; s++) {
        int i  = s * 256 + tid;
        int nr = i >> 3;
        int c8 = i & 7;
        uint4 u = *(const uint4*)&T[nr][c8 * 8];
        *(uint4*)&Wt[(size_t)(n0 + nr) * EMB + k0 + c8 * 8] = u;
    }
}

// ---------------------------------------------------------------------------
// fp16 GEMM, cp.async + ldmatrix.  C[M,N] = A[M,K] * Wt[N,K]^T.
// 128x128 block tile, BK=32, 256 threads (8 warps, 2x4 grid, 64x32 per warp),
// 3-stage cp.async pipeline, XOR-swizzled smem, ldmatrix fragments.
// k-accumulation order per output element identical to the 4-warp version
// (sequential over ci, then ks) -> bitwise-identical results.
// blockIdx.z selects (A0,W0,C0) / (A1,W1,C1) so K+V projections fuse.
// ---------------------------------------------------------------------------
template<bool HALF_OUT>
__global__ void __launch_bounds__(256)
gemm_h(const __half* __restrict__ A0, const __half* __restrict__ A1,
       const __half* __restrict__ W0, const __half* __restrict__ W1,
       void* C0v, void* C1v, int M, int N, int K, float oscale)
{
    __shared__ __align__(16) __half smA[3][128 * 32];
    __shared__ __align__(16) __half smB[3][128 * 32];

    const __half* A = blockIdx.z ? A1 : A0;
    const __half* W = blockIdx.z ? W1 : W0;
    void* Cv        = blockIdx.z ? C1v : C0v;

    const int tid  = threadIdx.x;
    const int lane = tid & 31;
    const int warp = tid >> 5;
    const int wm = warp >> 2, wn = warp & 3;   // 2 x 4 warp grid
    const int g = lane >> 2, j = lane & 3;
    const int bm = blockIdx.y * 128, bn = blockIdx.x * 128;

    const unsigned sA = (unsigned)__cvta_generic_to_shared(&smA[0][0]);
    const unsigned sB = (unsigned)__cvta_generic_to_shared(&smB[0][0]);

    // loader: 256 threads; each does 2 A + 2 B 16B-chunks per stage
    const int lc = tid & 3;       // chunk 0..3
    const int lr = tid >> 2;      // row 0..63 (and +64)

    auto issue = [&](int st, int k0) {
        int sw = lc ^ ((lr >> 1) & 3);     // (lr+64)>>1 has same low bits
        unsigned so0 = (unsigned)(st * 8192 + lr * 64 + sw * 16);
        unsigned so1 = (unsigned)(st * 8192 + (lr + 64) * 64 + sw * 16);
        cpa16(sA + so0, A + (size_t)(bm + lr) * K + k0 + lc * 8);
        cpa16(sA + so1, A + (size_t)(bm + lr + 64) * K + k0 + lc * 8);
        cpa16(sB + so0, W + (size_t)(bn + lr) * K + k0 + lc * 8);
        cpa16(sB + so1, W + (size_t)(bn + lr + 64) * K + k0 + lc * 8);
        asm volatile("cp.async.commit_group;" ::: "memory");
    };

    float c[4][4][4];
    #pragma unroll
    for (int mt = 0; mt < 4; mt++)
        #pragma unroll
        for (int nt = 0; nt < 4; nt++)
            #pragma unroll
            for (int e = 0; e < 4; e++) c[mt][nt][e] = 0.f;

    const int nc = K / 32;
    issue(0, 0);
    issue(1, 32);

    // fragment lane addressing (constant per thread)
    int rowAf[4], rowBf[2];
    #pragma unroll
    for (int mt = 0; mt < 4; mt++) rowAf[mt] = wm * 64 + mt * 16 + (lane & 15);
    #pragma unroll
    for (int ntp = 0; ntp < 2; ntp++)
        rowBf[ntp] = wn * 32 + ntp * 16 + (lane & 7) + ((lane >> 4) << 3);
    const int chA = lane >> 4;          // + ks*2
    const int chB = (lane >> 3) & 1;    // + ks*2

    for (int ci = 0; ci < nc; ci++) {
        if (ci == nc - 1) asm volatile("cp.async.wait_group 0;" ::: "memory");
        else              asm volatile("cp.async.wait_group 1;" ::: "memory");
        __syncthreads();
        if (ci + 2 < nc) issue((ci + 2) % 3, (ci + 2) * 32);

        const unsigned baseA = sA + (ci % 3) * 8192;
        const unsigned baseB = sB + (ci % 3) * 8192;

        #pragma unroll
        for (int ks = 0; ks < 2; ks++) {
            unsigned af[4][4], bf[2][4];
            #pragma unroll
            for (int mt = 0; mt < 4; mt++) {
                int ch = ks * 2 + chA;
                ldm_x4(af[mt], baseA + rowAf[mt] * 64 +
                               16 * (ch ^ ((rowAf[mt] >> 1) & 3)));
            }
            #pragma unroll
            for (int ntp = 0; ntp < 2; ntp++) {
                int ch = ks * 2 + chB;
                ldm_x4(bf[ntp], baseB + rowBf[ntp] * 64 +
                                16 * (ch ^ ((rowBf[ntp] >> 1) & 3)));
            }
            #pragma unroll
            for (int mt = 0; mt < 4; mt++)
                #pragma unroll
                for (int ntp = 0; ntp < 2; ntp++) {
                    mma16(c[mt][2 * ntp],     af[mt][0], af[mt][1], af[mt][2], af[mt][3],
                          bf[ntp][0], bf[ntp][1]);
                    mma16(c[mt][2 * ntp + 1], af[mt][0], af[mt][1], af[mt][2], af[mt][3],
                          bf[ntp][2], bf[ntp][3]);
                }
        }
    }

    if (HALF_OUT) {
        __half* Ch = (__half*)Cv;
        #pragma unroll
        for (int mt = 0; mt < 4; mt++) {
            int r0 = bm + wm * 64 + mt * 16 + g;
            #pragma unroll
            for (int nt = 0; nt < 4; nt++) {
                int col = bn + wn * 32 + nt * 8 + 2 * j;
                *(unsigned*)&Ch[(size_t)r0 * N + col] =
                    packh2(c[mt][nt][0] * oscale, c[mt][nt][1] * oscale);
                *(unsigned*)&Ch[(size_t)(r0 + 8) * N + col] =
                    packh2(c[mt][nt][2] * oscale, c[mt][nt][3] * oscale);
            }
        }
    } else {
        float* Cf = (float*)Cv;
        #pragma unroll
        for (int mt = 0; mt < 4; mt++) {
            int r0 = bm + wm * 64 + mt * 16 + g;
            #pragma unroll
            for (int nt = 0; nt < 4; nt++) {
                int col = bn + wn * 32 + nt * 8 + 2 * j;
                *(float2*)&Cf[(size_t)r0 * N + col] =
                    make_float2(c[mt][nt][0], c[mt][nt][1]);
                *(float2*)&Cf[(size_t)(r0 + 8) * N + col] =
                    make_float2(c[mt][nt][2], c[mt][nt][3]);
            }
        }
    }
}

// ---------------------------------------------------------------------------
// Flash attention, fp16 mma, GQA-shared K/V, P in registers.
// Block = (32 q-rows x 4 q-heads of one kv head), 256 thr, 8 warps.
// K and V tiles stored RAW [64 tok][64 half], XOR-swizzled (chunk ^= tok&7),
// filled by 3-stage cp.async pipeline. Score B-frags via ldmatrix; PV
// B-frags via ldmatrix.trans. (Unchanged from R9 — proven.)
// ---------------------------------------------------------------------------
__global__ void __launch_bounds__(256, 2)
attn_f16(const __half* __restrict__ Qh, const __half* __restrict__ Kh,
         const __half* __restrict__ Vh, __half* __restrict__ ctx)
{
    __shared__ __align__(16) __half Kb[3][64 * 64];
    __shared__ __align__(16) __half Vb[3][64 * 64];

    const int tid  = threadIdx.x;
    const int lane = tid & 31;
    const int warp = tid >> 5;
    const int g = lane >> 2, j = lane & 3;
    const int kvh = blockIdx.y, b = blockIdx.z;
    const int h  = kvh * 4 + (warp >> 1);
    const int q0 = blockIdx.x * 32 + (warp & 1) * 16;

    const unsigned sK = (unsigned)__cvta_generic_to_shared(&Kb[0][0]);
    const unsigned sV = (unsigned)__cvta_generic_to_shared(&Vb[0][0]);

    const __half* kbase = Kh + ((size_t)b * S) * KV_DIM + kvh * HD;
    const __half* vbase = Vh + ((size_t)b * S) * KV_DIM + kvh * HD;

    auto issue = [&](int st, int tk0) {
        #pragma unroll
        for (int i = 0; i < 2; i++) {
            int it  = i * 256 + tid;
            int tok = it >> 3, ch = it & 7;
            unsigned off = (unsigned)(st * 8192 + tok * 128 + 16 * (ch ^ (tok & 7)));
            size_t go = (size_t)(tk0 + tok) * KV_DIM + ch * 8;
            cpa16(sK + off, kbase + go);
            cpa16(sV + off, vbase + go);
        }
        asm volatile("cp.async.commit_group;" ::: "memory");
    };

    // Q fragments (already scaled by QSCALE at projection time)
    unsigned qa[4][4];
    {
        const __half* qp = Qh + ((size_t)(b * S + q0 + g)) * EMB + h * HD;
        #pragma unroll
        for (int t = 0; t < 4; t++) {
            int d0 = t * 16 + 2 * j;
            qa[t][0] = *(const unsigned*)&qp[d0];
            qa[t][1] = *(const unsigned*)&qp[(size_t)8 * EMB + d0];
            qa[t][2] = *(const unsigned*)&qp[d0 + 8];
            qa[t][3] = *(const unsigned*)&qp[(size_t)8 * EMB + d0 + 8];
        }
    }

    float m0 = -1e30f, m1 = -1e30f, l0 = 0.f, l1 = 0.f;
    float o[8][4];
    #pragma unroll
    for (int nt = 0; nt < 8; nt++)
        #pragma unroll
        for (int e = 0; e < 4; e++) o[nt][e] = 0.f;

    const int rowKf = (lane & 7) + ((lane >> 4) << 3);    // + ntp*16
    const int chKf  = (lane >> 3) & 1;                    // + ks*2
    const int rowVf = lane & 15;                          // + ks*16
    const int chVf  = lane >> 4;                          // + ntp*2

    const int nc = S / 64;    // 32 chunks
    issue(0, 0);
    issue(1, 64);

    for (int ci = 0; ci < nc; ci++) {
        if (ci == nc - 1) asm volatile("cp.async.wait_group 0;" ::: "memory");
        else              asm volatile("cp.async.wait_group 1;" ::: "memory");
        __syncthreads();
        if (ci + 2 < nc) issue((ci + 2) % 3, (ci + 2) * 64);

        const unsigned baseK = sK + (ci % 3) * 8192;
        const unsigned baseV = sV + (ci % 3) * 8192;

        // --- scores: S = Q * K^T (16 x 64 per warp) ---
        float s[8][4];
        #pragma unroll
        for (int nt = 0; nt < 8; nt++)
            #pragma unroll
            for (int e = 0; e < 4; e++) s[nt][e] = 0.f;

        #pragma unroll
        for (int ks = 0; ks < 4; ks++) {
            #pragma unroll
            for (int ntp = 0; ntp < 4; ntp++) {
                unsigned kb[4];
                int row = ntp * 16 + rowKf;
                int ch  = ks * 2 + chKf;
                ldm_x4(kb, baseK + row * 128 + 16 * (ch ^ (row & 7)));
                mma16(s[2 * ntp],     qa[ks][0], qa[ks][1], qa[ks][2], qa[ks][3],
                      kb[0], kb[1]);
                mma16(s[2 * ntp + 1], qa[ks][0], qa[ks][1], qa[ks][2], qa[ks][3],
                      kb[2], kb[3]);
            }
        }

        // --- online softmax (log2 domain); P stays in registers ---
        float r0 = -1e30f, r1 = -1e30f;
        #pragma unroll
        for (int nt = 0; nt < 8; nt++) {
            r0 = fmaxf(r0, fmaxf(s[nt][0], s[nt][1]));
            r1 = fmaxf(r1, fmaxf(s[nt][2], s[nt][3]));
        }
        r0 = fmaxf(r0, __shfl_xor_sync(0xffffffffu, r0, 1));
        r0 = fmaxf(r0, __shfl_xor_sync(0xffffffffu, r0, 2));
        r1 = fmaxf(r1, __shfl_xor_sync(0xffffffffu, r1, 1));
        r1 = fmaxf(r1, __shfl_xor_sync(0xffffffffu, r1, 2));
        float mn0 = fmaxf(m0, r0), mn1 = fmaxf(m1, r1);
        float sc0 = ex2f_fast(m0 - mn0), sc1 = ex2f_fast(m1 - mn1);
        unsigned pa0[8], pa1[8];
        float rs0 = 0.f, rs1 = 0.f;
        #pragma unroll
        for (int nt = 0; nt < 8; nt++) {
            float p0 = ex2f_fast(s[nt][0] - mn0);
            float p1 = ex2f_fast(s[nt][1] - mn0);
            float p2 = ex2f_fast(s[nt][2] - mn1);
            float p3 = ex2f_fast(s[nt][3] - mn1);
            rs0 += p0 + p1; rs1 += p2 + p3;
            pa0[nt] = packh2(p0, p1);
            pa1[nt] = packh2(p2, p3);
            o[nt][0] *= sc0; o[nt][1] *= sc0;
            o[nt][2] *= sc1; o[nt][3] *= sc1;
        }
        rs0 += __shfl_xor_sync(0xffffffffu, rs0, 1);
        rs0 += __shfl_xor_sync(0xffffffffu, rs0, 2);
        rs1 += __shfl_xor_sync(0xffffffffu, rs1, 1);
        rs1 += __shfl_xor_sync(0xffffffffu, rs1, 2);
        l0 = l0 * sc0 + rs0; m0 = mn0;
        l1 = l1 * sc1 + rs1; m1 = mn1;

        // --- O += P * V (V B-frags via ldmatrix.trans on raw rows) ---
        #pragma unroll
        for (int ks = 0; ks < 4; ks++) {
            #pragma unroll
            for (int ntp = 0; ntp < 4; ntp++) {
                unsigned vb[4];
                int row = ks * 16 + rowVf;
                int ch  = ntp * 2 + chVf;
                ldm_x4t(vb, baseV + row * 128 + 16 * (ch ^ (row & 7)));
                mma16(o[2 * ntp],     pa0[2 * ks], pa1[2 * ks],
                      pa0[2 * ks + 1], pa1[2 * ks + 1], vb[0], vb[1]);
                mma16(o[2 * ntp + 1], pa0[2 * ks], pa1[2 * ks],
                      pa0[2 * ks + 1], pa1[2 * ks + 1], vb[2], vb[3]);
            }
        }
    }

    // --- normalize + store (fp16 ctx) ---
    float inv0 = 1.f / l0, inv1 = 1.f / l1;
    size_t row = (size_t)(b * S + q0 + g);
    #pragma unroll
    for (int nt = 0; nt < 8; nt++) {
        int col = h * HD + nt * 8 + 2 * j;
        *(unsigned*)&ctx[row * EMB + col] =
            packh2(o[nt][0] * inv0, o[nt][1] * inv0);
        *(unsigned*)&ctx[(row + 8) * EMB + col] =
            packh2(o[nt][2] * inv1, o[nt][3] * inv1);
    }
}

// ---------------------------------------------------------------------------
extern "C" void kernel_launch(void* const* d_in, const int* in_sizes, int n_in,
                              void* d_out, int out_size)
{
    const float* query = (const float*)d_in[0];
    const float* key   = (const float*)d_in[1];
    const float* value = (const float*)d_in[2];
    const float* Wq    = (const float*)d_in[3];
    const float* Wk    = (const float*)d_in[4];
    const float* Wv    = (const float*)d_in[5];
    const float* Wo    = (const float*)d_in[6];
    float* out = (float*)d_out;

    __half *pXq, *pXk, *pXv, *pWq, *pWk, *pWv, *pWo, *pQ, *pK, *pV, *pCtx;
    cudaGetSymbolAddress((void**)&pXq, h_Xq);
    cudaGetSymbolAddress((void**)&pXk, h_Xk);
    cudaGetSymbolAddress((void**)&pXv, h_Xv);
    cudaGetSymbolAddress((void**)&pWq, h_Wq);
    cudaGetSymbolAddress((void**)&pWk, h_Wk);
    cudaGetSymbolAddress((void**)&pWv, h_Wv);
    cudaGetSymbolAddress((void**)&pWo, h_Wo);
    cudaGetSymbolAddress((void**)&pQ,  h_Q);
    cudaGetSymbolAddress((void**)&pK,  h_K);
    cudaGetSymbolAddress((void**)&pV,  h_V);
    cudaGetSymbolAddress((void**)&pCtx, h_Ctx);

    // fp32 -> fp16 precompute (inputs + transposed weights; fused pairs)
    cvt_x<<<dim3(M_ROWS * EMB / 8 / 256, 1, 3), 256>>>(
        query, key, value, pXq, pXk, pXv);
    cvt_wT<<<dim3(EMB / 64,    EMB / 64, 2), 256>>>(Wq, Wo, pWq, pWo, EMB);
    cvt_wT<<<dim3(KV_DIM / 64, EMB / 64, 2), 256>>>(Wk, Wv, pWk, pWv, KV_DIM);

    // Q projection (writes half, pre-scaled for softmax)
    gemm_h<true><<<dim3(EMB / 128, M_ROWS / 128, 1), 256>>>(
        pXq, pXq, pWq, pWq, pQ, pQ, M_ROWS, EMB, EMB, QSCALE);
    // K and V projections fused (z=0: key@Wk, z=1: value@Wv)
    gemm_h<true><<<dim3(KV_DIM / 128, M_ROWS / 128, 2), 256>>>(
        pXk, pXv, pWk, pWv, pK, pV, M_ROWS, KV_DIM, EMB, 1.0f);

    // Attention (cp.async-pipelined K/V, ldmatrix/.trans fragments)
    attn_f16<<<dim3(S / 32, NKV, B), 256>>>(pQ, pK, pV, pCtx);

    // Output projection (fp32 out)
    gemm_h<false><<<dim3(EMB / 128, M_ROWS / 128, 1), 256>>>(
        pCtx, pCtx, pWo, pWo, out, out, M_ROWS, EMB, EMB, 1.0f);
}

// round 17
// speedup vs baseline: 4.2898x; 1.0525x over previous
#include <cuda_runtime.h>
#include <cuda_fp16.h>
#include <math.h>

// Problem constants
#define B 2
#define S 2048
#define EMB 2048
#define NH 32
#define NKV 8
#define HD 64
#define KV_DIM (NKV * HD)   // 512
#define M_ROWS (B * S)      // 4096

#define QSCALE (0.125f * 1.4426950408889634f)

// Scratch (device globals; no allocation allowed). All half.
__device__ __half h_Xq[M_ROWS * EMB];     // inputs converted to fp16
__device__ __half h_Xk[M_ROWS * EMB];
__device__ __half h_Xv[M_ROWS * EMB];
__device__ __half h_Wq[EMB * EMB];        // weights transposed [N][K], fp16
__device__ __half h_Wk[KV_DIM * EMB];
__device__ __half h_Wv[KV_DIM * EMB];
__device__ __half h_Wo[EMB * EMB];
__device__ __half h_Q[M_ROWS * EMB];      // Q projection (pre-scaled)
__device__ __half h_K[M_ROWS * KV_DIM];
__device__ __half h_V[M_ROWS * KV_DIM];
__device__ __half h_Ctx[M_ROWS * EMB];    // attention context

// ---------------------------------------------------------------------------
// Helpers
// ---------------------------------------------------------------------------
__device__ __forceinline__ unsigned packh2(float a, float b) {
    __half2 h = __floats2half2_rn(a, b);
    return *reinterpret_cast<unsigned*>(&h);
}
__device__ __forceinline__ float ex2f_fast(float x) {
    float r; asm("ex2.approx.f32 %0, %1;" : "=f"(r) : "f"(x)); return r;
}
// D += A(16x16,row) * B(16x8,col), fp16 inputs, f32 accum
__device__ __forceinline__ void mma16(float* c, unsigned a0, unsigned a1,
                                      unsigned a2, unsigned a3,
                                      unsigned b0, unsigned b1) {
    asm volatile(
        "mma.sync.aligned.m16n8k16.row.col.f32.f16.f16.f32 "
        "{%0,%1,%2,%3}, {%4,%5,%6,%7}, {%8,%9}, {%0,%1,%2,%3};"
        : "+f"(c[0]), "+f"(c[1]), "+f"(c[2]), "+f"(c[3])
        : "r"(a0), "r"(a1), "r"(a2), "r"(a3), "r"(b0), "r"(b1));
}
__device__ __forceinline__ void ldm_x4(unsigned* r, unsigned addr) {
    asm volatile("ldmatrix.sync.aligned.m8n8.x4.shared.b16 {%0,%1,%2,%3}, [%4];"
                 : "=r"(r[0]), "=r"(r[1]), "=r"(r[2]), "=r"(r[3]) : "r"(addr));
}
__device__ __forceinline__ void ldm_x4t(unsigned* r, unsigned addr) {
    asm volatile("ldmatrix.sync.aligned.m8n8.x4.trans.shared.b16 {%0,%1,%2,%3}, [%4];"
                 : "=r"(r[0]), "=r"(r[1]), "=r"(r[2]), "=r"(r[3]) : "r"(addr));
}
__device__ __forceinline__ void cpa16(unsigned s, const void* g) {
    asm volatile("cp.async.cg.shared.global [%0], [%1], 16;" :: "r"(s), "l"(g) : "memory");
}

// ---------------------------------------------------------------------------
// Precompute: fp32 -> fp16 input copies (query/key/value picked by blockIdx.z)
// ---------------------------------------------------------------------------
__global__ void __launch_bounds__(256)
cvt_x(const float* __restrict__ x0, const float* __restrict__ x1,
      const float* __restrict__ x2,
      __half* __restrict__ y0, __half* __restrict__ y1, __half* __restrict__ y2)
{
    const float* x = (blockIdx.z == 0) ? x0 : (blockIdx.z == 1) ? x1 : x2;
    __half*      y = (blockIdx.z == 0) ? y0 : (blockIdx.z == 1) ? y1 : y2;
    size_t i = ((size_t)blockIdx.x * 256 + threadIdx.x) * 8;
    float4 v0 = *(const float4*)&x[i];
    float4 v1 = *(const float4*)&x[i + 4];
    uint4 u;
    u.x = packh2(v0.x, v0.y); u.y = packh2(v0.z, v0.w);
    u.z = packh2(v1.x, v1.y); u.w = packh2(v1.z, v1.w);
    *(uint4*)&y[i] = u;
}

// ---------------------------------------------------------------------------
// Precompute: all 4 weights W [K=2048][N] fp32 -> Wt [N][2048] fp16, fused.
// blockIdx.x < 32: Wq/Wo (N=2048); else Wk/Wv (N=512). blockIdx.z picks pair.
// ---------------------------------------------------------------------------
__global__ void __launch_bounds__(256)
cvt_w(const float* __restrict__ Wq, const float* __restrict__ Wo,
      const float* __restrict__ Wk, const float* __restrict__ Wv,
      __half* __restrict__ Tq, __half* __restrict__ To,
      __half* __restrict__ Tk, __half* __restrict__ Tv)
{
    const float* W; __half* Wt; int N, n0;
    const int x = blockIdx.x;
    if (x < 32) { W = blockIdx.z ? Wo : Wq; Wt = blockIdx.z ? To : Tq; N = EMB;    n0 = x * 64; }
    else        { W = blockIdx.z ? Wv : Wk; Wt = blockIdx.z ? Tv : Tk; N = KV_DIM; n0 = (x - 32) * 64; }
    __shared__ __half T[64][72];
    const int tid = threadIdx.x;
    const int k0 = blockIdx.y * 64;
    #pragma unroll
    for (int s = 0; s < 4; s++) {
        int i  = s * 256 + tid;
        int kr = i >> 4;
        int c4 = (i & 15) * 4;
        float4 v = *(const float4*)&W[(size_t)(k0 + kr) * N + n0 + c4];
        T[c4 + 0][kr] = __float2half(v.x);
        T[c4 + 1][kr] = __float2half(v.y);
        T[c4 + 2][kr] = __float2half(v.z);
        T[c4 + 3][kr] = __float2half(v.w);
    }
    __syncthreads();
    #pragma unroll
    for (int s = 0; s < 2; s++) {
        int i  = s * 256 + tid;
        int nr = i >> 3;
        int c8 = i & 7;
        uint4 u = *(const uint4*)&T[nr][c8 * 8];
        *(uint4*)&Wt[(size_t)(n0 + nr) * EMB + k0 + c8 * 8] = u;
    }
}

// ---------------------------------------------------------------------------
// fp16 GEMM body, cp.async + ldmatrix.  C[*,N] tile = A[M,2048] * Wt[N,2048]^T.
// 128x128 block tile, BK=32, 256 threads (8 warps, 2x4 grid, 64x32 per warp),
// 3-stage cp.async pipeline, XOR-swizzled smem, ldmatrix fragments.
// (Identical math/order to R13 gemm_h -> bitwise-identical results.)
// ---------------------------------------------------------------------------
template<bool HALF_OUT>
__device__ __forceinline__ void gemm_body(const __half* __restrict__ A,
                                          const __half* __restrict__ W,
                                          void* Cv, int N, int bm, int bn,
                                          float oscale)
{
    __shared__ __align__(16) __half smA[3][128 * 32];
    __shared__ __align__(16) __half smB[3][128 * 32];

    const int tid  = threadIdx.x;
    const int lane = tid & 31;
    const int warp = tid >> 5;
    const int wm = warp >> 2, wn = warp & 3;   // 2 x 4 warp grid
    const int g = lane >> 2, j = lane & 3;

    const unsigned sA = (unsigned)__cvta_generic_to_shared(&smA[0][0]);
    const unsigned sB = (unsigned)__cvta_generic_to_shared(&smB[0][0]);

    // loader: 256 threads; each does 2 A + 2 B 16B-chunks per stage
    const int lc = tid & 3;       // chunk 0..3
    const int lr = tid >> 2;      // row 0..63 (and +64)

    auto issue = [&](int st, int k0) {
        int sw = lc ^ ((lr >> 1) & 3);
        unsigned so0 = (unsigned)(st * 8192 + lr * 64 + sw * 16);
        unsigned so1 = (unsigned)(st * 8192 + (lr + 64) * 64 + sw * 16);
        cpa16(sA + so0, A + (size_t)(bm + lr) * EMB + k0 + lc * 8);
        cpa16(sA + so1, A + (size_t)(bm + lr + 64) * EMB + k0 + lc * 8);
        cpa16(sB + so0, W + (size_t)(bn + lr) * EMB + k0 + lc * 8);
        cpa16(sB + so1, W + (size_t)(bn + lr + 64) * EMB + k0 + lc * 8);
        asm volatile("cp.async.commit_group;" ::: "memory");
    };

    float c[4][4][4];
    #pragma unroll
    for (int mt = 0; mt < 4; mt++)
        #pragma unroll
        for (int nt = 0; nt < 4; nt++)
            #pragma unroll
            for (int e = 0; e < 4; e++) c[mt][nt][e] = 0.f;

    const int nc = EMB / 32;    // 64
    issue(0, 0);
    issue(1, 32);

    // fragment lane addressing (constant per thread)
    int rowAf[4], rowBf[2];
    #pragma unroll
    for (int mt = 0; mt < 4; mt++) rowAf[mt] = wm * 64 + mt * 16 + (lane & 15);
    #pragma unroll
    for (int ntp = 0; ntp < 2; ntp++)
        rowBf[ntp] = wn * 32 + ntp * 16 + (lane & 7) + ((lane >> 4) << 3);
    const int chA = lane >> 4;          // + ks*2
    const int chB = (lane >> 3) & 1;    // + ks*2

    for (int ci = 0; ci < nc; ci++) {
        if (ci == nc - 1) asm volatile("cp.async.wait_group 0;" ::: "memory");
        else              asm volatile("cp.async.wait_group 1;" ::: "memory");
        __syncthreads();
        if (ci + 2 < nc) issue((ci + 2) % 3, (ci + 2) * 32);

        const unsigned baseA = sA + (ci % 3) * 8192;
        const unsigned baseB = sB + (ci % 3) * 8192;

        #pragma unroll
        for (int ks = 0; ks < 2; ks++) {
            unsigned af[4][4], bf[2][4];
            #pragma unroll
            for (int mt = 0; mt < 4; mt++) {
                int ch = ks * 2 + chA;
                ldm_x4(af[mt], baseA + rowAf[mt] * 64 +
                               16 * (ch ^ ((rowAf[mt] >> 1) & 3)));
            }
            #pragma unroll
            for (int ntp = 0; ntp < 2; ntp++) {
                int ch = ks * 2 + chB;
                ldm_x4(bf[ntp], baseB + rowBf[ntp] * 64 +
                                16 * (ch ^ ((rowBf[ntp] >> 1) & 3)));
            }
            #pragma unroll
            for (int mt = 0; mt < 4; mt++)
                #pragma unroll
                for (int ntp = 0; ntp < 2; ntp++) {
                    mma16(c[mt][2 * ntp],     af[mt][0], af[mt][1], af[mt][2], af[mt][3],
                          bf[ntp][0], bf[ntp][1]);
                    mma16(c[mt][2 * ntp + 1], af[mt][0], af[mt][1], af[mt][2], af[mt][3],
                          bf[ntp][2], bf[ntp][3]);
                }
        }
    }

    if (HALF_OUT) {
        __half* Ch = (__half*)Cv;
        #pragma unroll
        for (int mt = 0; mt < 4; mt++) {
            int r0 = bm + wm * 64 + mt * 16 + g;
            #pragma unroll
            for (int nt = 0; nt < 4; nt++) {
                int col = bn + wn * 32 + nt * 8 + 2 * j;
                *(unsigned*)&Ch[(size_t)r0 * N + col] =
                    packh2(c[mt][nt][0] * oscale, c[mt][nt][1] * oscale);
                *(unsigned*)&Ch[(size_t)(r0 + 8) * N + col] =
                    packh2(c[mt][nt][2] * oscale, c[mt][nt][3] * oscale);
            }
        }
    } else {
        float* Cf = (float*)Cv;
        #pragma unroll
        for (int mt = 0; mt < 4; mt++) {
            int r0 = bm + wm * 64 + mt * 16 + g;
            #pragma unroll
            for (int nt = 0; nt < 4; nt++) {
                int col = bn + wn * 32 + nt * 8 + 2 * j;
                *(float2*)&Cf[(size_t)r0 * N + col] =
                    make_float2(c[mt][nt][0], c[mt][nt][1]);
                *(float2*)&Cf[(size_t)(r0 + 8) * N + col] =
                    make_float2(c[mt][nt][2], c[mt][nt][3]);
            }
        }
    }
}

// All three projections fused in one launch:
// blockIdx.x < 16: Q@Wq (N=2048, pre-scaled); <20: K@Wk; else V@Wv (N=512).
__global__ void __launch_bounds__(256)
proj_h(const __half* __restrict__ Xq, const __half* __restrict__ Xk,
       const __half* __restrict__ Xv,
       const __half* __restrict__ Wq, const __half* __restrict__ Wk,
       const __half* __restrict__ Wv,
       __half* __restrict__ Qo, __half* __restrict__ Ko, __half* __restrict__ Vo)
{
    const __half *A, *W; __half* C; int N, bn; float osc;
    const int x = blockIdx.x;
    if (x < 16)      { A = Xq; W = Wq; C = Qo; N = EMB;    bn = x * 128;        osc = QSCALE; }
    else if (x < 20) { A = Xk; W = Wk; C = Ko; N = KV_DIM; bn = (x - 16) * 128; osc = 1.0f; }
    else             { A = Xv; W = Wv; C = Vo; N = KV_DIM; bn = (x - 20) * 128; osc = 1.0f; }
    gemm_body<true>(A, W, C, N, blockIdx.y * 128, bn, osc);
}

// Output projection (fp32 out)
__global__ void __launch_bounds__(256)
oproj_h(const __half* __restrict__ Ctx, const __half* __restrict__ Wo,
        float* __restrict__ out)
{
    gemm_body<false>(Ctx, Wo, out, EMB, blockIdx.y * 128, blockIdx.x * 128, 1.0f);
}

// ---------------------------------------------------------------------------
// Flash attention, fp16 mma, GQA-shared K/V, P in registers.
// Block = (32 q-rows x 4 q-heads of one kv head), 256 thr, 8 warps.
// K and V tiles stored RAW [64 tok][64 half], XOR-swizzled (chunk ^= tok&7),
// filled by 3-stage cp.async pipeline. Score B-frags via ldmatrix; PV
// B-frags via ldmatrix.trans. Exact skip-rescale when the running max
// is unchanged warp-wide (rescale factor == 1.0 -> identity).
// ---------------------------------------------------------------------------
__global__ void __launch_bounds__(256, 2)
attn_f16(const __half* __restrict__ Qh, const __half* __restrict__ Kh,
         const __half* __restrict__ Vh, __half* __restrict__ ctx)
{
    __shared__ __align__(16) __half Kb[3][64 * 64];
    __shared__ __align__(16) __half Vb[3][64 * 64];

    const int tid  = threadIdx.x;
    const int lane = tid & 31;
    const int warp = tid >> 5;
    const int g = lane >> 2, j = lane & 3;
    const int kvh = blockIdx.y, b = blockIdx.z;
    const int h  = kvh * 4 + (warp >> 1);
    const int q0 = blockIdx.x * 32 + (warp & 1) * 16;

    const unsigned sK = (unsigned)__cvta_generic_to_shared(&Kb[0][0]);
    const unsigned sV = (unsigned)__cvta_generic_to_shared(&Vb[0][0]);

    const __half* kbase = Kh + ((size_t)b * S) * KV_DIM + kvh * HD;
    const __half* vbase = Vh + ((size_t)b * S) * KV_DIM + kvh * HD;

    auto issue = [&](int st, int tk0) {
        #pragma unroll
        for (int i = 0; i < 2; i++) {
            int it  = i * 256 + tid;
            int tok = it >> 3, ch = it & 7;
            unsigned off = (unsigned)(st * 8192 + tok * 128 + 16 * (ch ^ (tok & 7)));
            size_t go = (size_t)(tk0 + tok) * KV_DIM + ch * 8;
            cpa16(sK + off, kbase + go);
            cpa16(sV + off, vbase + go);
        }
        asm volatile("cp.async.commit_group;" ::: "memory");
    };

    // Q fragments (already scaled by QSCALE at projection time)
    unsigned qa[4][4];
    {
        const __half* qp = Qh + ((size_t)(b * S + q0 + g)) * EMB + h * HD;
        #pragma unroll
        for (int t = 0; t < 4; t++) {
            int d0 = t * 16 + 2 * j;
            qa[t][0] = *(const unsigned*)&qp[d0];
            qa[t][1] = *(const unsigned*)&qp[(size_t)8 * EMB + d0];
            qa[t][2] = *(const unsigned*)&qp[d0 + 8];
            qa[t][3] = *(const unsigned*)&qp[(size_t)8 * EMB + d0 + 8];
        }
    }

    float m0 = -1e30f, m1 = -1e30f, l0 = 0.f, l1 = 0.f;
    float o[8][4];
    #pragma unroll
    for (int nt = 0; nt < 8; nt++)
        #pragma unroll
        for (int e = 0; e < 4; e++) o[nt][e] = 0.f;

    const int rowKf = (lane & 7) + ((lane >> 4) << 3);    // + ntp*16
    const int chKf  = (lane >> 3) & 1;                    // + ks*2
    const int rowVf = lane & 15;                          // + ks*16
    const int chVf  = lane >> 4;                          // + ntp*2

    const int nc = S / 64;    // 32 chunks
    issue(0, 0);
    issue(1, 64);

    for (int ci = 0; ci < nc; ci++) {
        if (ci == nc - 1) asm volatile("cp.async.wait_group 0;" ::: "memory");
        else              asm volatile("cp.async.wait_group 1;" ::: "memory");
        __syncthreads();
        if (ci + 2 < nc) issue((ci + 2) % 3, (ci + 2) * 64);

        const unsigned baseK = sK + (ci % 3) * 8192;
        const unsigned baseV = sV + (ci % 3) * 8192;

        // --- scores: S = Q * K^T (16 x 64 per warp) ---
        float s[8][4];
        #pragma unroll
        for (int nt = 0; nt < 8; nt++)
            #pragma unroll
            for (int e = 0; e < 4; e++) s[nt][e] = 0.f;

        #pragma unroll
        for (int ks = 0; ks < 4; ks++) {
            #pragma unroll
            for (int ntp = 0; ntp < 4; ntp++) {
                unsigned kb[4];
                int row = ntp * 16 + rowKf;
                int ch  = ks * 2 + chKf;
                ldm_x4(kb, baseK + row * 128 + 16 * (ch ^ (row & 7)));
                mma16(s[2 * ntp],     qa[ks][0], qa[ks][1], qa[ks][2], qa[ks][3],
                      kb[0], kb[1]);
                mma16(s[2 * ntp + 1], qa[ks][0], qa[ks][1], qa[ks][2], qa[ks][3],
                      kb[2], kb[3]);
            }
        }

        // --- online softmax (log2 domain); P stays in registers ---
        float r0 = -1e30f, r1 = -1e30f;
        #pragma unroll
        for (int nt = 0; nt < 8; nt++) {
            r0 = fmaxf(r0, fmaxf(s[nt][0], s[nt][1]));
            r1 = fmaxf(r1, fmaxf(s[nt][2], s[nt][3]));
        }
        r0 = fmaxf(r0, __shfl_xor_sync(0xffffffffu, r0, 1));
        r0 = fmaxf(r0, __shfl_xor_sync(0xffffffffu, r0, 2));
        r1 = fmaxf(r1, __shfl_xor_sync(0xffffffffu, r1, 1));
        r1 = fmaxf(r1, __shfl_xor_sync(0xffffffffu, r1, 2));
        float mn0 = fmaxf(m0, r0), mn1 = fmaxf(m1, r1);

        // Exact skip: if max unchanged warp-wide, rescale factor is exactly 1.
        bool norsc = __all_sync(0xffffffffu, (mn0 == m0) && (mn1 == m1));

        unsigned pa0[8], pa1[8];
        float rs0 = 0.f, rs1 = 0.f;
        #pragma unroll
        for (int nt = 0; nt < 8; nt++) {
            float p0 = ex2f_fast(s[nt][0] - mn0);
            float p1 = ex2f_fast(s[nt][1] - mn0);
            float p2 = ex2f_fast(s[nt][2] - mn1);
            float p3 = ex2f_fast(s[nt][3] - mn1);
            rs0 += p0 + p1; rs1 += p2 + p3;
            pa0[nt] = packh2(p0, p1);
            pa1[nt] = packh2(p2, p3);
        }
        rs0 += __shfl_xor_sync(0xffffffffu, rs0, 1);
        rs0 += __shfl_xor_sync(0xffffffffu, rs0, 2);
        rs1 += __shfl_xor_sync(0xffffffffu, rs1, 1);
        rs1 += __shfl_xor_sync(0xffffffffu, rs1, 2);
        if (!norsc) {
            float sc0 = ex2f_fast(m0 - mn0), sc1 = ex2f_fast(m1 - mn1);
            #pragma unroll
            for (int nt = 0; nt < 8; nt++) {
                o[nt][0] *= sc0; o[nt][1] *= sc0;
                o[nt][2] *= sc1; o[nt][3] *= sc1;
            }
            l0 = l0 * sc0 + rs0;
            l1 = l1 * sc1 + rs1;
        } else {
            l0 = l0 + rs0;
            l1 = l1 + rs1;
        }
        m0 = mn0; m1 = mn1;

        // --- O += P * V (V B-frags via ldmatrix.trans on raw rows) ---
        #pragma unroll
        for (int ks = 0; ks < 4; ks++) {
            #pragma unroll
            for (int ntp = 0; ntp < 4; ntp++) {
                unsigned vb[4];
                int row = ks * 16 + rowVf;
                int ch  = ntp * 2 + chVf;
                ldm_x4t(vb, baseV + row * 128 + 16 * (ch ^ (row & 7)));
                mma16(o[2 * ntp],     pa0[2 * ks], pa1[2 * ks],
                      pa0[2 * ks + 1], pa1[2 * ks + 1], vb[0], vb[1]);
                mma16(o[2 * ntp + 1], pa0[2 * ks], pa1[2 * ks],
                      pa0[2 * ks + 1], pa1[2 * ks + 1], vb[2], vb[3]);
            }
        }
    }

    // --- normalize + store (fp16 ctx) ---
    float inv0 = 1.f / l0, inv1 = 1.f / l1;
    size_t row = (size_t)(b * S + q0 + g);
    #pragma unroll
    for (int nt = 0; nt < 8; nt++) {
        int col = h * HD + nt * 8 + 2 * j;
        *(unsigned*)&ctx[row * EMB + col] =
            packh2(o[nt][0] * inv0, o[nt][1] * inv0);
        *(unsigned*)&ctx[(row + 8) * EMB + col] =
            packh2(o[nt][2] * inv1, o[nt][3] * inv1);
    }
}

// ---------------------------------------------------------------------------
extern "C" void kernel_launch(void* const* d_in, const int* in_sizes, int n_in,
                              void* d_out, int out_size)
{
    const float* query = (const float*)d_in[0];
    const float* key   = (const float*)d_in[1];
    const float* value = (const float*)d_in[2];
    const float* Wq    = (const float*)d_in[3];
    const float* Wk    = (const float*)d_in[4];
    const float* Wv    = (const float*)d_in[5];
    const float* Wo    = (const float*)d_in[6];
    float* out = (float*)d_out;

    __half *pXq, *pXk, *pXv, *pWq, *pWk, *pWv, *pWo, *pQ, *pK, *pV, *pCtx;
    cudaGetSymbolAddress((void**)&pXq, h_Xq);
    cudaGetSymbolAddress((void**)&pXk, h_Xk);
    cudaGetSymbolAddress((void**)&pXv, h_Xv);
    cudaGetSymbolAddress((void**)&pWq, h_Wq);
    cudaGetSymbolAddress((void**)&pWk, h_Wk);
    cudaGetSymbolAddress((void**)&pWv, h_Wv);
    cudaGetSymbolAddress((void**)&pWo, h_Wo);
    cudaGetSymbolAddress((void**)&pQ,  h_Q);
    cudaGetSymbolAddress((void**)&pK,  h_K);
    cudaGetSymbolAddress((void**)&pV,  h_V);
    cudaGetSymbolAddress((void**)&pCtx, h_Ctx);

    // fp32 -> fp16 precompute (inputs; all 4 weights fused in one launch)
    cvt_x<<<dim3(M_ROWS * EMB / 8 / 256, 1, 3), 256>>>(
        query, key, value, pXq, pXk, pXv);
    cvt_w<<<dim3(40, EMB / 64, 2), 256>>>(Wq, Wo, Wk, Wv, pWq, pWo, pWk, pWv);

    // Q + K + V projections fused in ONE launch (x-partitioned)
    proj_h<<<dim3(24, M_ROWS / 128), 256>>>(
        pXq, pXk, pXv, pWq, pWk, pWv, pQ, pK, pV);

    // Attention (cp.async-pipelined K/V, ldmatrix/.trans fragments, skip-rescale)
    attn_f16<<<dim3(S / 32, NKV, B), 256>>>(pQ, pK, pV, pCtx);

    // Output projection (fp32 out)
    oproj_h<<<dim3(EMB / 128, M_ROWS / 128), 256>>>(pCtx, pWo, out);
}